// round 13
// baseline (speedup 1.0000x reference)
#include <cuda_runtime.h>
#include <cuda_fp16.h>
#include <cstdint>

#define NTILES 512
#define NB     54

// ========================= device scratch (fp16 images) =====================
__device__ __align__(16) __half g_w1h[NB * 8192];  // O_w1: [j=128][k=64], k57=Ob1
__device__ __align__(16) __half g_w2i[NB * 1024];  // O_w2: [n=8][k=128] (n<3 live)
__device__ __align__(16) __half g_bn1[8192];       // N_w1
__device__ __align__(16) __half g_bn2[8192];       // N_w2
__device__ __align__(16) __half g_bf1[8192];       // F_w1
__device__ __align__(16) __half g_bf2[8192];       // F_w2
__device__ __align__(16) __half g_fimg[NTILES * 8192]; // f images (swizzled, col57=1)

// ============================= PTX helpers =================================
__device__ __forceinline__ uint32_t smem_u32(const void* p) {
    uint32_t a;
    asm("{ .reg .u64 t; cvta.to.shared.u64 t, %1; cvt.u32.u64 %0, t; }"
        : "=r"(a) : "l"(p));
    return a;
}
__device__ __forceinline__ void ldsm_x4(uint32_t addr, uint32_t& r0, uint32_t& r1,
                                        uint32_t& r2, uint32_t& r3) {
    asm volatile("ldmatrix.sync.aligned.m8n8.x4.shared.b16 {%0,%1,%2,%3}, [%4];"
                 : "=r"(r0), "=r"(r1), "=r"(r2), "=r"(r3) : "r"(addr));
}
__device__ __forceinline__ void mma16816(float& d0, float& d1, float& d2, float& d3,
                                         uint32_t a0, uint32_t a1, uint32_t a2, uint32_t a3,
                                         uint32_t b0, uint32_t b1) {
    asm volatile("mma.sync.aligned.m16n8k16.row.col.f32.f16.f16.f32 "
                 "{%0,%1,%2,%3}, {%4,%5,%6,%7}, {%8,%9}, {%0,%1,%2,%3};"
                 : "+f"(d0), "+f"(d1), "+f"(d2), "+f"(d3)
                 : "r"(a0), "r"(a1), "r"(a2), "r"(a3), "r"(b0), "r"(b1));
}
__device__ __forceinline__ void mma16808(float& d0, float& d1, float& d2, float& d3,
                                         uint32_t a0, uint32_t a1, uint32_t b0) {
    asm volatile("mma.sync.aligned.m16n8k8.row.col.f32.f16.f16.f32 "
                 "{%0,%1,%2,%3}, {%4,%5}, {%6}, {%0,%1,%2,%3};"
                 : "+f"(d0), "+f"(d1), "+f"(d2), "+f"(d3)
                 : "r"(a0), "r"(a1), "r"(b0));
}
__device__ __forceinline__ uint32_t sw128(uint32_t off) {
    return off ^ ((off >> 3) & 0x70);
}
__device__ __forceinline__ uint32_t packh2(float lo, float hi) {
    __half2 h = __floats2half2_rn(lo, hi);
    return *reinterpret_cast<uint32_t*>(&h);
}

// ============================================================================
// Convert weights -> swizzled fp16 images (biases baked at constant-1 k-col).
// ============================================================================
__global__ __launch_bounds__(256) void k_convert(
    const float* __restrict__ Ow1, const float* __restrict__ Ob1,
    const float* __restrict__ Ow2,
    const float* __restrict__ Nw1, const float* __restrict__ Nb1,
    const float* __restrict__ Nw2,
    const float* __restrict__ Fw1, const float* __restrict__ Fb1,
    const float* __restrict__ Fw2)
{
    int idx = blockIdx.x * 256 + threadIdx.x;
    if (idx < NB * 8192) {
        int j = idx & 127, k = (idx >> 7) & 63, n = idx >> 13;
        float v = (k < 57) ? Ow1[n * 7296 + k * 128 + j]
                 : (k == 57 ? Ob1[n * 128 + j] : 0.f);
        g_w1h[n * 8192 + (sw128((unsigned)(j * 128 + k * 2)) >> 1)] = __float2half(v);
        return;
    }
    int t = idx - NB * 8192;
    if (t < 4 * 8192) {
        int img = t >> 13, e = t & 8191;
        if (img == 0) {
            int j = e >> 6, k = e & 63;
            float v = (k < 54) ? Nw1[k * 128 + j] : (k == 54 ? Nb1[j] : 0.f);
            g_bn1[sw128((unsigned)(j * 128 + k * 2)) >> 1] = __float2half(v);
        } else if (img == 1) {
            int j = e >> 6, k = e & 63;
            float v = (k < 57) ? Fw1[k * 128 + j] : (k == 57 ? Fb1[j] : 0.f);
            g_bf1[sw128((unsigned)(j * 128 + k * 2)) >> 1] = __float2half(v);
        } else if (img == 2) {
            int m = e >> 7, k = e & 127;
            float v = (m < 54) ? Nw2[k * 54 + m] : 0.f;
            g_bn2[sw128((unsigned)(m * 256 + k * 2)) >> 1] = __float2half(v);
        } else {
            int m = e >> 7, k = e & 127;
            float v = (m < 57) ? Fw2[k * 57 + m] : 0.f;
            g_bf2[sw128((unsigned)(m * 256 + k * 2)) >> 1] = __float2half(v);
        }
        return;
    }
    t -= 4 * 8192;
    if (t >= NB * 1024) return;
    {
        int n = t >> 10, e = t & 1023;
        int m = e >> 7, k = e & 127;
        float v = (m < 3) ? Ow2[n * 384 + k * 3 + m] : 0.f;
        g_w2i[n * 1024 + (sw128((unsigned)(m * 256 + k * 2)) >> 1)] = __float2half(v);
    }
}

// ==================== features-kernel SMEM layout (91.2 KB, 2 CTAs/SM) ======
#define FX    0
#define FWA   16384
#define FWB   32768
#define FH0   49152
#define FH1   65536
#define FXC   81920
#define FCW1  83968
#define FCW2  86016
#define FCB1  88064
#define FCB2  88576
#define FBN2  88608
#define FBF2  88864
#define FCP   89120
#define F_TOT 91168

// ---- 8-warp layer: 64-K HMMA, 128 out cols, relu (bias baked) -> H0/H1 -----
__device__ __forceinline__ void layer_wide8(
    uint32_t sA, uint32_t sB, char* h0, char* h1, int wid, int lane)
{
    const int m01 = (lane >> 3) & 1, kh = lane >> 4;
    const int quad = lane & 3, qrow = lane >> 2;
    const int bjrow = lane & 7, bkt = lane >> 4, bkh = (lane >> 3) & 1;
    const int rg = wid * 16 + (lane & 7) + (m01 << 3);

    uint32_t a[4][4];
#pragma unroll
    for (int kt = 0; kt < 4; ++kt) {
        uint32_t off = sw128((uint32_t)(rg * 128 + kt * 32 + kh * 16));
        ldsm_x4(sA + off, a[kt][0], a[kt][1], a[kt][2], a[kt][3]);
    }
#pragma unroll 4
    for (int nt = 0; nt < 16; ++nt) {
        uint32_t off0 = sw128((uint32_t)((nt * 8 + bjrow) * 128 + bkt * 32 + bkh * 16));
        uint32_t off1 = sw128((uint32_t)((nt * 8 + bjrow) * 128 + (bkt + 2) * 32 + bkh * 16));
        uint32_t b[4][2];
        ldsm_x4(sB + off0, b[0][0], b[0][1], b[1][0], b[1][1]);
        ldsm_x4(sB + off1, b[2][0], b[2][1], b[3][0], b[3][1]);
        float d0 = 0.f, d1 = 0.f, d2 = 0.f, d3 = 0.f;
#pragma unroll
        for (int kt = 0; kt < 4; ++kt)
            mma16816(d0, d1, d2, d3, a[kt][0], a[kt][1], a[kt][2], a[kt][3],
                     b[kt][0], b[kt][1]);
        int j0 = nt * 8 + quad * 2;
        char* himg = (j0 < 64) ? h0 : h1;
        int   jc   = j0 & 63;
        int rA = wid * 16 + qrow, rB = rA + 8;
        *(__half2*)(himg + sw128((uint32_t)(rA * 128 + jc * 2))) =
            __floats2half2_rn(fmaxf(d0, 0.f), fmaxf(d1, 0.f));
        *(__half2*)(himg + sw128((uint32_t)(rB * 128 + jc * 2))) =
            __floats2half2_rn(fmaxf(d2, 0.f), fmaxf(d3, 0.f));
    }
}

// ---- 8-warp layer: 128-K HMMA (H halves), bias, fp16 -> outimg -------------
__device__ __forceinline__ void layer_narrow8(
    uint32_t sH0, uint32_t sH1, uint32_t sB, const float* __restrict__ bias,
    char* outimg, int coff, int mlim, int ntn, int wid, int lane)
{
    const int m01 = (lane >> 3) & 1, kh = lane >> 4;
    const int quad = lane & 3, qrow = lane >> 2;
    const int bjrow = lane & 7, bkt = lane >> 4, bkh = (lane >> 3) & 1;
    const int rg = wid * 16 + (lane & 7) + (m01 << 3);

    uint32_t a[8][4];
#pragma unroll
    for (int kt = 0; kt < 8; ++kt) {
        uint32_t src = (kt < 4) ? sH0 : sH1;
        int      ktl = kt & 3;
        uint32_t off = sw128((uint32_t)(rg * 128 + ktl * 32 + kh * 16));
        ldsm_x4(src + off, a[kt][0], a[kt][1], a[kt][2], a[kt][3]);
    }
    for (int nt = 0; nt < ntn; ++nt) {
        uint32_t b[8][2];
#pragma unroll
        for (int q = 0; q < 4; ++q) {
            uint32_t off = sw128((uint32_t)((nt * 8 + bjrow) * 256 + q * 64 + bkt * 32 + bkh * 16));
            ldsm_x4(sB + off, b[2 * q][0], b[2 * q][1], b[2 * q + 1][0], b[2 * q + 1][1]);
        }
        float d0 = 0.f, d1 = 0.f, d2 = 0.f, d3 = 0.f;
#pragma unroll
        for (int kt = 0; kt < 8; ++kt)
            mma16816(d0, d1, d2, d3, a[kt][0], a[kt][1], a[kt][2], a[kt][3],
                     b[kt][0], b[kt][1]);
        int m0 = nt * 8 + quad * 2, m1 = m0 + 1;
        int rA = wid * 16 + qrow, rB = rA + 8;
        if (m0 < mlim) {
            *(__half*)(outimg + sw128((uint32_t)(rA * 128 + (m0 + coff) * 2))) =
                __float2half(d0 + bias[m0]);
            *(__half*)(outimg + sw128((uint32_t)(rB * 128 + (m0 + coff) * 2))) =
                __float2half(d2 + bias[m0]);
        }
        if (m1 < mlim) {
            *(__half*)(outimg + sw128((uint32_t)(rA * 128 + (m1 + coff) * 2))) =
                __float2half(d1 + bias[m1]);
            *(__half*)(outimg + sw128((uint32_t)(rB * 128 + (m1 + coff) * 2))) =
                __float2half(d3 + bias[m1]);
        }
    }
}

__device__ __forceinline__ void softmax_store(float* __restrict__ out,
                                              size_t row, int n,
                                              float l0, float l1, float l2)
{
    float mx = fmaxf(l0, fmaxf(l1, l2));
    float e0 = __expf(l0 - mx), e1 = __expf(l1 - mx), e2 = __expf(l2 - mx);
    float inv = 1.f / (e0 + e1 + e2);
    float* o = out + row * 162 + n * 3;
    o[0] = e0 * inv; o[1] = e1 * inv; o[2] = e2 * inv;
}

// ============================================================================
// Kernel 1: features, 256 threads / 8 warps, 128 rows (unchanged from R12).
// ============================================================================
__global__ void __launch_bounds__(256, 2) k_features(
    const float* __restrict__ x,
    const float* __restrict__ Cw1, const float* __restrict__ Cb1v,
    const float* __restrict__ Cw2, const float* __restrict__ Cb2v,
    const float* __restrict__ Nb2v, const float* __restrict__ Fb2v)
{
    extern __shared__ char smem[];
    const uint32_t sbase = smem_u32(smem);
    float* xc   = (float*)(smem + FXC);
    float* cw1t = (float*)(smem + FCW1);
    float* cw2  = (float*)(smem + FCW2);
    float* cb1  = (float*)(smem + FCB1);
    float* cb2  = (float*)(smem + FCB2);
    float* bn2  = (float*)(smem + FBN2);
    float* bf2  = (float*)(smem + FBF2);
    float* cp   = (float*)(smem + FCP);

    const int tid  = threadIdx.x;
    const int wid  = tid >> 5;
    const int lane = tid & 31;
    const int row0 = blockIdx.x * 128;

    for (int i = tid; i < 128 * 58; i += 256) {
        int r = i / 58, c = i - r * 58;
        float v = x[(size_t)(row0 + r) * 58 + c];
        if (c < 4) xc[r * 4 + c] = v;
        else *(__half*)(smem + FX + sw128((uint32_t)(r * 128 + (c - 4) * 2))) =
                 __float2half(v);
    }
    for (int i = tid; i < 128 * 10; i += 256) {
        int r = i / 10, kk = 54 + (i - (i / 10) * 10);
        float v = (kk == 54 || kk == 57) ? 1.f : 0.f;
        *(__half*)(smem + FX + sw128((uint32_t)(r * 128 + kk * 2))) = __float2half(v);
    }
    {
        const uint4* sa = (const uint4*)g_bn1; uint4* da = (uint4*)(smem + FWA);
        const uint4* sb = (const uint4*)g_bn2; uint4* db = (uint4*)(smem + FWB);
#pragma unroll
        for (int i = 0; i < 4; ++i) {
            da[tid + 256 * i] = sa[tid + 256 * i];
            db[tid + 256 * i] = sb[tid + 256 * i];
        }
    }
    if (tid < 128) cb1[tid] = Cb1v[tid];
    else if (tid < 192) {
        int t = tid - 128;
        bn2[t] = (t < 54) ? Nb2v[t] : 0.f;
        bf2[t] = (t < 57) ? Fb2v[t] : 0.f;
    } else if (tid < 196) {
        int t = tid - 192;
        cb2[t] = (t < 3) ? Cb2v[t] : 0.f;
    }
    for (int i = tid; i < 512; i += 256) { int k = i >> 7, j = i & 127; cw1t[j * 4 + k] = Cw1[i]; }
    for (int i = tid; i < 384; i += 256) { int j = i / 3, m = i - j * 3; cw2[j * 4 + m] = Cw2[i]; }
    __syncthreads();

    const int crow = tid & 127, cjh = tid >> 7;
    float c0, c1, c2;
    {
        float cx0 = xc[crow * 4 + 0], cx1 = xc[crow * 4 + 1];
        float cx2 = xc[crow * 4 + 2], cx3 = xc[crow * 4 + 3];
        c0 = cjh ? 0.f : cb2[0];
        c1 = cjh ? 0.f : cb2[1];
        c2 = cjh ? 0.f : cb2[2];
        const int j0 = cjh * 64;
        for (int j = j0; j < j0 + 64; ++j) {
            const float* w = &cw1t[j * 4];
            float h = cb1[j] + cx0 * w[0] + cx1 * w[1] + cx2 * w[2] + cx3 * w[3];
            h = fmaxf(h, 0.f);
            const float* w2 = &cw2[j * 4];
            c0 += h * w2[0]; c1 += h * w2[1]; c2 += h * w2[2];
        }
        if (cjh) {
            cp[crow * 4 + 0] = c0; cp[crow * 4 + 1] = c1; cp[crow * 4 + 2] = c2;
        }
    }

    layer_wide8(sbase + FX, sbase + FWA, smem + FH0, smem + FH1, wid, lane);
    __syncthreads();

    {
        const uint4* s = (const uint4*)g_bf1; uint4* d = (uint4*)(smem + FWA);
#pragma unroll
        for (int i = 0; i < 4; ++i) d[tid + 256 * i] = s[tid + 256 * i];
    }
    layer_narrow8(sbase + FH0, sbase + FH1, sbase + FWB, bn2,
                  smem + FX, 3, 54, 7, wid, lane);
    if (!cjh) {
        float f0 = c0 + cp[crow * 4 + 0];
        float f1 = c1 + cp[crow * 4 + 1];
        float f2 = c2 + cp[crow * 4 + 2];
        *(__half*)(smem + FX + sw128((uint32_t)(crow * 128 + 0))) = __float2half(f0);
        *(__half*)(smem + FX + sw128((uint32_t)(crow * 128 + 2))) = __float2half(f1);
        *(__half*)(smem + FX + sw128((uint32_t)(crow * 128 + 4))) = __float2half(f2);
    }
    __syncthreads();

    {
        const uint4* s = (const uint4*)g_bf2; uint4* d = (uint4*)(smem + FWB);
#pragma unroll
        for (int i = 0; i < 4; ++i) d[tid + 256 * i] = s[tid + 256 * i];
    }
    layer_wide8(sbase + FX, sbase + FWA, smem + FH0, smem + FH1, wid, lane);
    __syncthreads();

    layer_narrow8(sbase + FH0, sbase + FH1, sbase + FWB, bf2,
                  smem + FX, 0, 57, 8, wid, lane);
    __syncthreads();

    {
        const uint4* s = (const uint4*)(smem + FX);
        uint4* d = (uint4*)(g_fimg + (size_t)blockIdx.x * 8192);
#pragma unroll
        for (int i = 0; i < 4; ++i) d[tid + 256 * i] = s[tid + 256 * i];
    }
}

// ==================== O-kernel SMEM layout (106.5 KB, 2 CTAs/SM) ============
#define OG_A    0          // 32 KB: two A tile images
#define OG_B0   32768      // 32 KB: pairbuf0 (branches P,Q contiguous)
#define OG_B2   65536      // 32 KB: pairbuf1
#define OG_W2S  98304      // 8 KB
#define OG_TOT  106496

// ============================================================================
// Kernel 2: O stage, 256 threads / 8 warps / 256 rows.
// 2-D warp split: warp = (row-group 0..3, branch 0..1). Each warp: 64 rows
// (4 m-tiles) x 1 branch -> B-fragment smem traffic halved vs R12.
// Layer 2 via m16n8k8 consuming packed relu pairs immediately.
// ============================================================================
__global__ void __launch_bounds__(256, 2) k_ogemm(
    const float* __restrict__ Ob2, float* __restrict__ out)
{
    extern __shared__ char smem[];
    const uint32_t sbase = smem_u32(smem);

    const int tid  = threadIdx.x;
    const int wid  = tid >> 5;
    const int lane = tid & 31;
    const int row0 = blockIdx.x * 256;
    const int n0   = blockIdx.y * 6;
    const int rwid = wid & 3;        // row-group (64 rows)
    const int bsel = wid >> 2;       // branch within pair

    // ---- prologue: A images + pair0 (both branches) + W2 pair0 -------------
    {
        const uint4* sa = (const uint4*)(g_fimg + (size_t)blockIdx.x * 16384);
        uint4* dx = (uint4*)(smem + OG_A);
#pragma unroll
        for (int i = 0; i < 8; ++i) dx[tid + 256 * i] = sa[tid + 256 * i];
        const uint4* s0 = (const uint4*)(g_w1h + n0 * 8192);
        uint4* d0 = (uint4*)(smem + OG_B0);
#pragma unroll
        for (int i = 0; i < 8; ++i) d0[tid + 256 * i] = s0[tid + 256 * i];
        ((uint4*)(smem + OG_W2S))[tid] = ((const uint4*)(g_w2i + n0 * 1024))[tid];
    }
    __syncthreads();

    // ---- A fragments: warp owns rows rwid*64 .. rwid*64+63 (4 m-tiles) -----
    uint32_t a[4][4][4];
    {
        int m01 = (lane >> 3) & 1, kh = lane >> 4;
#pragma unroll
        for (int mt = 0; mt < 4; ++mt) {
            int rg = rwid * 64 + mt * 16 + (lane & 7) + (m01 << 3);
            uint32_t base = sbase + OG_A + (uint32_t)(rg >> 7) * 16384;
            int rl = rg & 127;
#pragma unroll
            for (int kt = 0; kt < 4; ++kt) {
                uint32_t off = sw128((uint32_t)(rl * 128 + kt * 32 + kh * 16));
                ldsm_x4(base + off,
                        a[mt][kt][0], a[mt][kt][1], a[mt][kt][2], a[mt][kt][3]);
            }
        }
    }

    const int quad = lane & 3;
    const int qrow = lane >> 2;
    const int bjrow = lane & 7;
    const int bkt   = lane >> 4;
    const int bkh   = (lane >> 3) & 1;
    const uint32_t w2rowb = (uint32_t)((lane & 7) * 256 + (lane >> 3) * 16);

    for (int p = 0; p < 3; ++p) {
        const int buf = p & 1, nxt = buf ^ 1;
        const int nP = n0 + 2 * p;
        const int n  = nP + bsel;         // this warp's branch

        if (p < 2) {
            const uint4* s0 = (const uint4*)(g_w1h + (nP + 2) * 8192);
            uint4* d0 = (uint4*)(smem + (nxt ? OG_B2 : OG_B0));
#pragma unroll
            for (int i = 0; i < 8; ++i) d0[tid + 256 * i] = s0[tid + 256 * i];
            ((uint4*)(smem + OG_W2S + nxt * 4096))[tid] =
                ((const uint4*)(g_w2i + (nP + 2) * 1024))[tid];
        }

        const uint32_t sb  = sbase + (buf ? OG_B2 : OG_B0) + (uint32_t)bsel * 16384;
        const uint32_t sw2 = sbase + OG_W2S + (uint32_t)buf * 4096 + (uint32_t)bsel * 2048;

        // logit accumulators for 4 m-tiles (init with Ob2 at thread's columns)
        float lg[4][4];
        {
            int cc0 = 2 * quad, cc1 = cc0 + 1;
            float v0 = (cc0 < 3) ? Ob2[n * 3 + cc0] : 0.f;
            float v1 = (cc1 < 3) ? Ob2[n * 3 + cc1] : 0.f;
#pragma unroll
            for (int mt = 0; mt < 4; ++mt) {
                lg[mt][0] = v0; lg[mt][1] = v1; lg[mt][2] = v0; lg[mt][3] = v1;
            }
        }

        uint32_t b2[2][2];
#pragma unroll 2
        for (int kt = 0; kt < 8; ++kt) {
            if ((kt & 1) == 0) {     // W2 frags for kt, kt+1 (two k8 each)
                uint32_t off = sw128(w2rowb + (uint32_t)(kt >> 1) * 64);
                ldsm_x4(sw2 + off, b2[0][0], b2[0][1], b2[1][0], b2[1][1]);
            }
#pragma unroll
            for (int e = 0; e < 2; ++e) {
                const int nt = 2 * kt + e;
                uint32_t off0 = sw128((uint32_t)((nt * 8 + bjrow) * 128 + bkt * 32 + bkh * 16));
                uint32_t off1 = sw128((uint32_t)((nt * 8 + bjrow) * 128 + (bkt + 2) * 32 + bkh * 16));
                uint32_t bt[4][2];
                ldsm_x4(sb + off0, bt[0][0], bt[0][1], bt[1][0], bt[1][1]);
                ldsm_x4(sb + off1, bt[2][0], bt[2][1], bt[3][0], bt[3][1]);
                const uint32_t b2e = b2[kt & 1][e];
#pragma unroll
                for (int mt = 0; mt < 4; ++mt) {
                    float d0 = 0.f, d1 = 0.f, d2 = 0.f, d3 = 0.f;
#pragma unroll
                    for (int k4 = 0; k4 < 4; ++k4)
                        mma16816(d0, d1, d2, d3,
                                 a[mt][k4][0], a[mt][k4][1], a[mt][k4][2], a[mt][k4][3],
                                 bt[k4][0], bt[k4][1]);
                    uint32_t p0 = packh2(fmaxf(d0, 0.f), fmaxf(d1, 0.f));
                    uint32_t p1 = packh2(fmaxf(d2, 0.f), fmaxf(d3, 0.f));
                    mma16808(lg[mt][0], lg[mt][1], lg[mt][2], lg[mt][3],
                             p0, p1, b2e);
                }
            }
        }

        // epilogue: quad1 holds col2; pull into quad0, softmax, store (branch n)
#pragma unroll
        for (int mt = 0; mt < 4; ++mt) {
            float t0 = __shfl_xor_sync(0xffffffffu, lg[mt][0], 1);
            float t2 = __shfl_xor_sync(0xffffffffu, lg[mt][2], 1);
            if (quad == 0) {
                size_t rA = (size_t)(row0 + rwid * 64 + mt * 16 + qrow);
                size_t rB = rA + 8;
                softmax_store(out, rA, n, lg[mt][0], lg[mt][1], t0);
                softmax_store(out, rB, n, lg[mt][2], lg[mt][3], t2);
            }
        }
        __syncthreads();
    }
}

// ============================================================================
extern "C" void kernel_launch(void* const* d_in, const int* in_sizes, int n_in,
                              void* d_out, int out_size)
{
    const float* x   = (const float*)d_in[0];
    const float* Cw1 = (const float*)d_in[1];
    const float* Cb1 = (const float*)d_in[2];
    const float* Cw2 = (const float*)d_in[3];
    const float* Cb2 = (const float*)d_in[4];
    const float* Nw1 = (const float*)d_in[5];
    const float* Nb1 = (const float*)d_in[6];
    const float* Nw2 = (const float*)d_in[7];
    const float* Nb2 = (const float*)d_in[8];
    const float* Fw1 = (const float*)d_in[9];
    const float* Fb1 = (const float*)d_in[10];
    const float* Fw2 = (const float*)d_in[11];
    const float* Fb2 = (const float*)d_in[12];
    const float* Ow1 = (const float*)d_in[13];
    const float* Ob1 = (const float*)d_in[14];
    const float* Ow2 = (const float*)d_in[15];
    const float* Ob2 = (const float*)d_in[16];
    float* out = (float*)d_out;

    cudaFuncSetAttribute(k_features, cudaFuncAttributeMaxDynamicSharedMemorySize, F_TOT);
    cudaFuncSetAttribute(k_ogemm,    cudaFuncAttributeMaxDynamicSharedMemorySize, OG_TOT);

    const int conv_elems = NB * 8192 + 4 * 8192 + NB * 1024;
    k_convert<<<(conv_elems + 255) / 256, 256>>>(Ow1, Ob1, Ow2, Nw1, Nb1, Nw2,
                                                 Fw1, Fb1, Fw2);

    k_features<<<NTILES, 256, F_TOT>>>(x, Cw1, Cb1, Cw2, Cb2, Nb2, Fb2);

    dim3 grid2(NTILES / 2, 9);
    k_ogemm<<<grid2, 256, OG_TOT>>>(Ob2, out);
}

// round 14
// speedup vs baseline: 1.0463x; 1.0463x over previous
#include <cuda_runtime.h>
#include <cuda_fp16.h>
#include <cstdint>

#define NTILES 512
#define NB     54

// ========================= device scratch (fp16 images) =====================
__device__ __align__(16) __half g_w1h[NB * 8192];  // O_w1: [j=128][k=64], k57=Ob1
__device__ __align__(16) __half g_w2i[NB * 1024];  // O_w2: [n=8][k=128] (n<3 live)
__device__ __align__(16) __half g_bn1[8192];       // N_w1
__device__ __align__(16) __half g_bn2[8192];       // N_w2
__device__ __align__(16) __half g_bf1[8192];       // F_w1
__device__ __align__(16) __half g_bf2[8192];       // F_w2
__device__ __align__(16) __half g_fimg[NTILES * 8192]; // f images (swizzled, col57=1)

// ============================= PTX helpers =================================
__device__ __forceinline__ uint32_t smem_u32(const void* p) {
    uint32_t a;
    asm("{ .reg .u64 t; cvta.to.shared.u64 t, %1; cvt.u32.u64 %0, t; }"
        : "=r"(a) : "l"(p));
    return a;
}
__device__ __forceinline__ void ldsm_x4(uint32_t addr, uint32_t& r0, uint32_t& r1,
                                        uint32_t& r2, uint32_t& r3) {
    asm volatile("ldmatrix.sync.aligned.m8n8.x4.shared.b16 {%0,%1,%2,%3}, [%4];"
                 : "=r"(r0), "=r"(r1), "=r"(r2), "=r"(r3) : "r"(addr));
}
__device__ __forceinline__ void mma16816(float& d0, float& d1, float& d2, float& d3,
                                         uint32_t a0, uint32_t a1, uint32_t a2, uint32_t a3,
                                         uint32_t b0, uint32_t b1) {
    asm volatile("mma.sync.aligned.m16n8k16.row.col.f32.f16.f16.f32 "
                 "{%0,%1,%2,%3}, {%4,%5,%6,%7}, {%8,%9}, {%0,%1,%2,%3};"
                 : "+f"(d0), "+f"(d1), "+f"(d2), "+f"(d3)
                 : "r"(a0), "r"(a1), "r"(a2), "r"(a3), "r"(b0), "r"(b1));
}
__device__ __forceinline__ void mma16808(float& d0, float& d1, float& d2, float& d3,
                                         uint32_t a0, uint32_t a1, uint32_t b0) {
    asm volatile("mma.sync.aligned.m16n8k8.row.col.f32.f16.f16.f32 "
                 "{%0,%1,%2,%3}, {%4,%5}, {%6}, {%0,%1,%2,%3};"
                 : "+f"(d0), "+f"(d1), "+f"(d2), "+f"(d3)
                 : "r"(a0), "r"(a1), "r"(b0));
}
__device__ __forceinline__ uint32_t sw128(uint32_t off) {
    return off ^ ((off >> 3) & 0x70);
}
__device__ __forceinline__ uint32_t packh2(float lo, float hi) {
    __half2 h = __floats2half2_rn(lo, hi);
    return *reinterpret_cast<uint32_t*>(&h);
}
#define CP_ASYNC16(dst, src) \
    asm volatile("cp.async.cg.shared.global [%0], [%1], 16;" \
                 :: "r"(dst), "l"(src) : "memory")
#define CP_COMMIT() asm volatile("cp.async.commit_group;" ::: "memory")
#define CP_WAIT0()  asm volatile("cp.async.wait_group 0;"  ::: "memory")

// ============================================================================
// Convert weights -> swizzled fp16 images (biases baked at constant-1 k-col).
// ============================================================================
__global__ __launch_bounds__(256) void k_convert(
    const float* __restrict__ Ow1, const float* __restrict__ Ob1,
    const float* __restrict__ Ow2,
    const float* __restrict__ Nw1, const float* __restrict__ Nb1,
    const float* __restrict__ Nw2,
    const float* __restrict__ Fw1, const float* __restrict__ Fb1,
    const float* __restrict__ Fw2)
{
    int idx = blockIdx.x * 256 + threadIdx.x;
    if (idx < NB * 8192) {
        int j = idx & 127, k = (idx >> 7) & 63, n = idx >> 13;
        float v = (k < 57) ? Ow1[n * 7296 + k * 128 + j]
                 : (k == 57 ? Ob1[n * 128 + j] : 0.f);
        g_w1h[n * 8192 + (sw128((unsigned)(j * 128 + k * 2)) >> 1)] = __float2half(v);
        return;
    }
    int t = idx - NB * 8192;
    if (t < 4 * 8192) {
        int img = t >> 13, e = t & 8191;
        if (img == 0) {
            int j = e >> 6, k = e & 63;
            float v = (k < 54) ? Nw1[k * 128 + j] : (k == 54 ? Nb1[j] : 0.f);
            g_bn1[sw128((unsigned)(j * 128 + k * 2)) >> 1] = __float2half(v);
        } else if (img == 1) {
            int j = e >> 6, k = e & 63;
            float v = (k < 57) ? Fw1[k * 128 + j] : (k == 57 ? Fb1[j] : 0.f);
            g_bf1[sw128((unsigned)(j * 128 + k * 2)) >> 1] = __float2half(v);
        } else if (img == 2) {
            int m = e >> 7, k = e & 127;
            float v = (m < 54) ? Nw2[k * 54 + m] : 0.f;
            g_bn2[sw128((unsigned)(m * 256 + k * 2)) >> 1] = __float2half(v);
        } else {
            int m = e >> 7, k = e & 127;
            float v = (m < 57) ? Fw2[k * 57 + m] : 0.f;
            g_bf2[sw128((unsigned)(m * 256 + k * 2)) >> 1] = __float2half(v);
        }
        return;
    }
    t -= 4 * 8192;
    if (t >= NB * 1024) return;
    {
        int n = t >> 10, e = t & 1023;
        int m = e >> 7, k = e & 127;
        float v = (m < 3) ? Ow2[n * 384 + k * 3 + m] : 0.f;
        g_w2i[n * 1024 + (sw128((unsigned)(m * 256 + k * 2)) >> 1)] = __float2half(v);
    }
}

// ==================== features-kernel SMEM layout (91.2 KB, 2 CTAs/SM) ======
#define FX    0
#define FWA   16384
#define FWB   32768
#define FH0   49152
#define FH1   65536
#define FXC   81920
#define FCW1  83968
#define FCW2  86016
#define FCB1  88064
#define FCB2  88576
#define FBN2  88608
#define FBF2  88864
#define FCP   89120
#define F_TOT 91168

// ---- 8-warp layer: 64-K HMMA, 128 out cols, relu (bias baked) -> H0/H1 -----
__device__ __forceinline__ void layer_wide8(
    uint32_t sA, uint32_t sB, char* h0, char* h1, int wid, int lane)
{
    const int m01 = (lane >> 3) & 1, kh = lane >> 4;
    const int quad = lane & 3, qrow = lane >> 2;
    const int bjrow = lane & 7, bkt = lane >> 4, bkh = (lane >> 3) & 1;
    const int rg = wid * 16 + (lane & 7) + (m01 << 3);

    uint32_t a[4][4];
#pragma unroll
    for (int kt = 0; kt < 4; ++kt) {
        uint32_t off = sw128((uint32_t)(rg * 128 + kt * 32 + kh * 16));
        ldsm_x4(sA + off, a[kt][0], a[kt][1], a[kt][2], a[kt][3]);
    }
#pragma unroll 4
    for (int nt = 0; nt < 16; ++nt) {
        uint32_t off0 = sw128((uint32_t)((nt * 8 + bjrow) * 128 + bkt * 32 + bkh * 16));
        uint32_t off1 = sw128((uint32_t)((nt * 8 + bjrow) * 128 + (bkt + 2) * 32 + bkh * 16));
        uint32_t b[4][2];
        ldsm_x4(sB + off0, b[0][0], b[0][1], b[1][0], b[1][1]);
        ldsm_x4(sB + off1, b[2][0], b[2][1], b[3][0], b[3][1]);
        float d0 = 0.f, d1 = 0.f, d2 = 0.f, d3 = 0.f;
#pragma unroll
        for (int kt = 0; kt < 4; ++kt)
            mma16816(d0, d1, d2, d3, a[kt][0], a[kt][1], a[kt][2], a[kt][3],
                     b[kt][0], b[kt][1]);
        int j0 = nt * 8 + quad * 2;
        char* himg = (j0 < 64) ? h0 : h1;
        int   jc   = j0 & 63;
        int rA = wid * 16 + qrow, rB = rA + 8;
        *(__half2*)(himg + sw128((uint32_t)(rA * 128 + jc * 2))) =
            __floats2half2_rn(fmaxf(d0, 0.f), fmaxf(d1, 0.f));
        *(__half2*)(himg + sw128((uint32_t)(rB * 128 + jc * 2))) =
            __floats2half2_rn(fmaxf(d2, 0.f), fmaxf(d3, 0.f));
    }
}

// ---- 8-warp layer: 128-K HMMA (H halves), bias, fp16 -> outimg -------------
__device__ __forceinline__ void layer_narrow8(
    uint32_t sH0, uint32_t sH1, uint32_t sB, const float* __restrict__ bias,
    char* outimg, int coff, int mlim, int ntn, int wid, int lane)
{
    const int m01 = (lane >> 3) & 1, kh = lane >> 4;
    const int quad = lane & 3, qrow = lane >> 2;
    const int bjrow = lane & 7, bkt = lane >> 4, bkh = (lane >> 3) & 1;
    const int rg = wid * 16 + (lane & 7) + (m01 << 3);

    uint32_t a[8][4];
#pragma unroll
    for (int kt = 0; kt < 8; ++kt) {
        uint32_t src = (kt < 4) ? sH0 : sH1;
        int      ktl = kt & 3;
        uint32_t off = sw128((uint32_t)(rg * 128 + ktl * 32 + kh * 16));
        ldsm_x4(src + off, a[kt][0], a[kt][1], a[kt][2], a[kt][3]);
    }
    for (int nt = 0; nt < ntn; ++nt) {
        uint32_t b[8][2];
#pragma unroll
        for (int q = 0; q < 4; ++q) {
            uint32_t off = sw128((uint32_t)((nt * 8 + bjrow) * 256 + q * 64 + bkt * 32 + bkh * 16));
            ldsm_x4(sB + off, b[2 * q][0], b[2 * q][1], b[2 * q + 1][0], b[2 * q + 1][1]);
        }
        float d0 = 0.f, d1 = 0.f, d2 = 0.f, d3 = 0.f;
#pragma unroll
        for (int kt = 0; kt < 8; ++kt)
            mma16816(d0, d1, d2, d3, a[kt][0], a[kt][1], a[kt][2], a[kt][3],
                     b[kt][0], b[kt][1]);
        int m0 = nt * 8 + quad * 2, m1 = m0 + 1;
        int rA = wid * 16 + qrow, rB = rA + 8;
        if (m0 < mlim) {
            *(__half*)(outimg + sw128((uint32_t)(rA * 128 + (m0 + coff) * 2))) =
                __float2half(d0 + bias[m0]);
            *(__half*)(outimg + sw128((uint32_t)(rB * 128 + (m0 + coff) * 2))) =
                __float2half(d2 + bias[m0]);
        }
        if (m1 < mlim) {
            *(__half*)(outimg + sw128((uint32_t)(rA * 128 + (m1 + coff) * 2))) =
                __float2half(d1 + bias[m1]);
            *(__half*)(outimg + sw128((uint32_t)(rB * 128 + (m1 + coff) * 2))) =
                __float2half(d3 + bias[m1]);
        }
    }
}

__device__ __forceinline__ void softmax_store(float* __restrict__ out,
                                              size_t row, int n,
                                              float l0, float l1, float l2)
{
    float mx = fmaxf(l0, fmaxf(l1, l2));
    float e0 = __expf(l0 - mx), e1 = __expf(l1 - mx), e2 = __expf(l2 - mx);
    float inv = 1.f / (e0 + e1 + e2);
    float* o = out + row * 162 + n * 3;
    o[0] = e0 * inv; o[1] = e1 * inv; o[2] = e2 * inv;
}

// ============================================================================
// Kernel 1: features, 256 threads / 8 warps, 128 rows (unchanged from R12).
// ============================================================================
__global__ void __launch_bounds__(256, 2) k_features(
    const float* __restrict__ x,
    const float* __restrict__ Cw1, const float* __restrict__ Cb1v,
    const float* __restrict__ Cw2, const float* __restrict__ Cb2v,
    const float* __restrict__ Nb2v, const float* __restrict__ Fb2v)
{
    extern __shared__ char smem[];
    const uint32_t sbase = smem_u32(smem);
    float* xc   = (float*)(smem + FXC);
    float* cw1t = (float*)(smem + FCW1);
    float* cw2  = (float*)(smem + FCW2);
    float* cb1  = (float*)(smem + FCB1);
    float* cb2  = (float*)(smem + FCB2);
    float* bn2  = (float*)(smem + FBN2);
    float* bf2  = (float*)(smem + FBF2);
    float* cp   = (float*)(smem + FCP);

    const int tid  = threadIdx.x;
    const int wid  = tid >> 5;
    const int lane = tid & 31;
    const int row0 = blockIdx.x * 128;

    for (int i = tid; i < 128 * 58; i += 256) {
        int r = i / 58, c = i - r * 58;
        float v = x[(size_t)(row0 + r) * 58 + c];
        if (c < 4) xc[r * 4 + c] = v;
        else *(__half*)(smem + FX + sw128((uint32_t)(r * 128 + (c - 4) * 2))) =
                 __float2half(v);
    }
    for (int i = tid; i < 128 * 10; i += 256) {
        int r = i / 10, kk = 54 + (i - (i / 10) * 10);
        float v = (kk == 54 || kk == 57) ? 1.f : 0.f;
        *(__half*)(smem + FX + sw128((uint32_t)(r * 128 + kk * 2))) = __float2half(v);
    }
    {
        const uint4* sa = (const uint4*)g_bn1; uint4* da = (uint4*)(smem + FWA);
        const uint4* sb = (const uint4*)g_bn2; uint4* db = (uint4*)(smem + FWB);
#pragma unroll
        for (int i = 0; i < 4; ++i) {
            da[tid + 256 * i] = sa[tid + 256 * i];
            db[tid + 256 * i] = sb[tid + 256 * i];
        }
    }
    if (tid < 128) cb1[tid] = Cb1v[tid];
    else if (tid < 192) {
        int t = tid - 128;
        bn2[t] = (t < 54) ? Nb2v[t] : 0.f;
        bf2[t] = (t < 57) ? Fb2v[t] : 0.f;
    } else if (tid < 196) {
        int t = tid - 192;
        cb2[t] = (t < 3) ? Cb2v[t] : 0.f;
    }
    for (int i = tid; i < 512; i += 256) { int k = i >> 7, j = i & 127; cw1t[j * 4 + k] = Cw1[i]; }
    for (int i = tid; i < 384; i += 256) { int j = i / 3, m = i - j * 3; cw2[j * 4 + m] = Cw2[i]; }
    __syncthreads();

    const int crow = tid & 127, cjh = tid >> 7;
    float c0, c1, c2;
    {
        float cx0 = xc[crow * 4 + 0], cx1 = xc[crow * 4 + 1];
        float cx2 = xc[crow * 4 + 2], cx3 = xc[crow * 4 + 3];
        c0 = cjh ? 0.f : cb2[0];
        c1 = cjh ? 0.f : cb2[1];
        c2 = cjh ? 0.f : cb2[2];
        const int j0 = cjh * 64;
        for (int j = j0; j < j0 + 64; ++j) {
            const float* w = &cw1t[j * 4];
            float h = cb1[j] + cx0 * w[0] + cx1 * w[1] + cx2 * w[2] + cx3 * w[3];
            h = fmaxf(h, 0.f);
            const float* w2 = &cw2[j * 4];
            c0 += h * w2[0]; c1 += h * w2[1]; c2 += h * w2[2];
        }
        if (cjh) {
            cp[crow * 4 + 0] = c0; cp[crow * 4 + 1] = c1; cp[crow * 4 + 2] = c2;
        }
    }

    layer_wide8(sbase + FX, sbase + FWA, smem + FH0, smem + FH1, wid, lane);
    __syncthreads();

    {
        const uint4* s = (const uint4*)g_bf1; uint4* d = (uint4*)(smem + FWA);
#pragma unroll
        for (int i = 0; i < 4; ++i) d[tid + 256 * i] = s[tid + 256 * i];
    }
    layer_narrow8(sbase + FH0, sbase + FH1, sbase + FWB, bn2,
                  smem + FX, 3, 54, 7, wid, lane);
    if (!cjh) {
        float f0 = c0 + cp[crow * 4 + 0];
        float f1 = c1 + cp[crow * 4 + 1];
        float f2 = c2 + cp[crow * 4 + 2];
        *(__half*)(smem + FX + sw128((uint32_t)(crow * 128 + 0))) = __float2half(f0);
        *(__half*)(smem + FX + sw128((uint32_t)(crow * 128 + 2))) = __float2half(f1);
        *(__half*)(smem + FX + sw128((uint32_t)(crow * 128 + 4))) = __float2half(f2);
    }
    __syncthreads();

    {
        const uint4* s = (const uint4*)g_bf2; uint4* d = (uint4*)(smem + FWB);
#pragma unroll
        for (int i = 0; i < 4; ++i) d[tid + 256 * i] = s[tid + 256 * i];
    }
    layer_wide8(sbase + FX, sbase + FWA, smem + FH0, smem + FH1, wid, lane);
    __syncthreads();

    layer_narrow8(sbase + FH0, sbase + FH1, sbase + FWB, bf2,
                  smem + FX, 0, 57, 8, wid, lane);
    __syncthreads();

    {
        const uint4* s = (const uint4*)(smem + FX);
        uint4* d = (uint4*)(g_fimg + (size_t)blockIdx.x * 8192);
#pragma unroll
        for (int i = 0; i < 4; ++i) d[tid + 256 * i] = s[tid + 256 * i];
    }
}

// ==================== O-kernel SMEM layout (106.5 KB, 2 CTAs/SM) ============
#define OG_A    0          // 32 KB: two A tile images
#define OG_B0   32768      // 32 KB: pairbuf0 (branches P,Q contiguous)
#define OG_B2   65536      // 32 KB: pairbuf1
#define OG_W2S  98304      // 8 KB
#define OG_TOT  106496

// ============================================================================
// Kernel 2: O stage, 256 threads / 8 warps / 256 rows, 2 CTAs/SM.
// R12 warp layout (warp = 32 rows x both branches) + immediate k8 layer-2
// (no staging arrays) + cp.async prefetch (register diet for scheduling slack).
// ============================================================================
__global__ void __launch_bounds__(256, 2) k_ogemm(
    const float* __restrict__ Ob2, float* __restrict__ out)
{
    extern __shared__ char smem[];
    const uint32_t sbase = smem_u32(smem);

    const int tid  = threadIdx.x;
    const int wid  = tid >> 5;
    const int lane = tid & 31;
    const int row0 = blockIdx.x * 256;
    const int n0   = blockIdx.y * 6;

    {
        const uint4* sa = (const uint4*)(g_fimg + (size_t)blockIdx.x * 16384);
        uint4* dx = (uint4*)(smem + OG_A);
#pragma unroll
        for (int i = 0; i < 8; ++i) dx[tid + 256 * i] = sa[tid + 256 * i];
        const uint4* s0 = (const uint4*)(g_w1h + n0 * 8192);
        uint4* d0 = (uint4*)(smem + OG_B0);
#pragma unroll
        for (int i = 0; i < 8; ++i) d0[tid + 256 * i] = s0[tid + 256 * i];
        ((uint4*)(smem + OG_W2S))[tid] = ((const uint4*)(g_w2i + n0 * 1024))[tid];
    }
    __syncthreads();

    uint32_t a[2][4][4];
    {
        int m01 = (lane >> 3) & 1, kh = lane >> 4;
#pragma unroll
        for (int mt = 0; mt < 2; ++mt) {
            int rg = wid * 32 + mt * 16 + (lane & 7) + (m01 << 3);
            uint32_t base = sbase + OG_A + (uint32_t)(rg >> 7) * 16384;
            int rl = rg & 127;
#pragma unroll
            for (int kt = 0; kt < 4; ++kt) {
                uint32_t off = sw128((uint32_t)(rl * 128 + kt * 32 + kh * 16));
                ldsm_x4(base + off,
                        a[mt][kt][0], a[mt][kt][1], a[mt][kt][2], a[mt][kt][3]);
            }
        }
    }

    const int quad = lane & 3;
    const int qrow = lane >> 2;
    const int bjrow = lane & 7;
    const int bkt   = lane >> 4;
    const int bkh   = (lane >> 3) & 1;
    const uint32_t w2rowb = (uint32_t)((lane & 7) * 256 + (lane >> 3) * 16);

    for (int p = 0; p < 3; ++p) {
        const int buf = p & 1, nxt = buf ^ 1;
        const int nP = n0 + 2 * p, nQ = nP + 1;

        // async prefetch next pair (B tiles + W2) — no register carriers
        if (p < 2) {
            uint32_t db = sbase + (nxt ? OG_B2 : OG_B0);
            const char* sg = (const char*)(g_w1h + (nP + 2) * 8192);
#pragma unroll
            for (int i = 0; i < 8; ++i) {
                uint32_t o = (uint32_t)(tid + 256 * i) * 16;
                CP_ASYNC16(db + o, sg + o);
            }
            uint32_t dw = sbase + OG_W2S + (uint32_t)nxt * 4096 + (uint32_t)tid * 16;
            CP_ASYNC16(dw, (const char*)(g_w2i + (nP + 2) * 1024) + tid * 16);
            CP_COMMIT();
        }

        const uint32_t sb0  = sbase + (buf ? OG_B2 : OG_B0);
        const uint32_t sb1  = sb0 + 16384;
        const uint32_t sw2P = sbase + OG_W2S + (uint32_t)buf * 4096;
        const uint32_t sw2Q = sw2P + 2048;

        float lgP[2][4], lgQ[2][4];
        {
            int cc0 = 2 * quad, cc1 = cc0 + 1;
            float p0 = (cc0 < 3) ? Ob2[nP * 3 + cc0] : 0.f;
            float p1 = (cc1 < 3) ? Ob2[nP * 3 + cc1] : 0.f;
            float q0 = (cc0 < 3) ? Ob2[nQ * 3 + cc0] : 0.f;
            float q1 = (cc1 < 3) ? Ob2[nQ * 3 + cc1] : 0.f;
#pragma unroll
            for (int mt = 0; mt < 2; ++mt) {
                lgP[mt][0] = p0; lgP[mt][1] = p1; lgP[mt][2] = p0; lgP[mt][3] = p1;
                lgQ[mt][0] = q0; lgQ[mt][1] = q1; lgQ[mt][2] = q0; lgQ[mt][3] = q1;
            }
        }

        uint32_t b2P[2][2], b2Q[2][2];
#pragma unroll
        for (int kt = 0; kt < 8; ++kt) {
            if ((kt & 1) == 0) {   // W2 frags for kt,kt+1 (each: two k8 regs)
                uint32_t off = sw128(w2rowb + (uint32_t)(kt >> 1) * 64);
                ldsm_x4(sw2P + off, b2P[0][0], b2P[0][1], b2P[1][0], b2P[1][1]);
                ldsm_x4(sw2Q + off, b2Q[0][0], b2Q[0][1], b2Q[1][0], b2Q[1][1]);
            }
#pragma unroll
            for (int e = 0; e < 2; ++e) {
                const int nt = 2 * kt + e;
                uint32_t off0 = sw128((uint32_t)((nt * 8 + bjrow) * 128 + bkt * 32 + bkh * 16));
                uint32_t off1 = sw128((uint32_t)((nt * 8 + bjrow) * 128 + (bkt + 2) * 32 + bkh * 16));
                uint32_t bP[4][2], bQ[4][2];
                ldsm_x4(sb0 + off0, bP[0][0], bP[0][1], bP[1][0], bP[1][1]);
                ldsm_x4(sb0 + off1, bP[2][0], bP[2][1], bP[3][0], bP[3][1]);
                ldsm_x4(sb1 + off0, bQ[0][0], bQ[0][1], bQ[1][0], bQ[1][1]);
                ldsm_x4(sb1 + off1, bQ[2][0], bQ[2][1], bQ[3][0], bQ[3][1]);
                const uint32_t b2Pe = b2P[kt & 1][e];
                const uint32_t b2Qe = b2Q[kt & 1][e];
#pragma unroll
                for (int mt = 0; mt < 2; ++mt) {
                    float dP0 = 0.f, dP1 = 0.f, dP2 = 0.f, dP3 = 0.f;
                    float dQ0 = 0.f, dQ1 = 0.f, dQ2 = 0.f, dQ3 = 0.f;
#pragma unroll
                    for (int k4 = 0; k4 < 4; ++k4) {
                        mma16816(dP0, dP1, dP2, dP3,
                                 a[mt][k4][0], a[mt][k4][1], a[mt][k4][2], a[mt][k4][3],
                                 bP[k4][0], bP[k4][1]);
                        mma16816(dQ0, dQ1, dQ2, dQ3,
                                 a[mt][k4][0], a[mt][k4][1], a[mt][k4][2], a[mt][k4][3],
                                 bQ[k4][0], bQ[k4][1]);
                    }
                    // layer 2: consume relu pairs immediately (k8 MMA)
                    {
                        uint32_t p0 = packh2(fmaxf(dP0, 0.f), fmaxf(dP1, 0.f));
                        uint32_t p1 = packh2(fmaxf(dP2, 0.f), fmaxf(dP3, 0.f));
                        mma16808(lgP[mt][0], lgP[mt][1], lgP[mt][2], lgP[mt][3],
                                 p0, p1, b2Pe);
                    }
                    {
                        uint32_t q0 = packh2(fmaxf(dQ0, 0.f), fmaxf(dQ1, 0.f));
                        uint32_t q1 = packh2(fmaxf(dQ2, 0.f), fmaxf(dQ3, 0.f));
                        mma16808(lgQ[mt][0], lgQ[mt][1], lgQ[mt][2], lgQ[mt][3],
                                 q0, q1, b2Qe);
                    }
                }
            }
        }

#pragma unroll
        for (int mt = 0; mt < 2; ++mt) {
            float tP0 = __shfl_xor_sync(0xffffffffu, lgP[mt][0], 1);
            float tP2 = __shfl_xor_sync(0xffffffffu, lgP[mt][2], 1);
            float tQ0 = __shfl_xor_sync(0xffffffffu, lgQ[mt][0], 1);
            float tQ2 = __shfl_xor_sync(0xffffffffu, lgQ[mt][2], 1);
            if (quad == 0) {
                size_t rA = (size_t)(row0 + wid * 32 + mt * 16 + qrow);
                size_t rB = rA + 8;
                softmax_store(out, rA, nP, lgP[mt][0], lgP[mt][1], tP0);
                softmax_store(out, rB, nP, lgP[mt][2], lgP[mt][3], tP2);
                softmax_store(out, rA, nQ, lgQ[mt][0], lgQ[mt][1], tQ0);
                softmax_store(out, rB, nQ, lgQ[mt][2], lgQ[mt][3], tQ2);
            }
        }
        if (p < 2) CP_WAIT0();
        __syncthreads();
    }
}

// ============================================================================
extern "C" void kernel_launch(void* const* d_in, const int* in_sizes, int n_in,
                              void* d_out, int out_size)
{
    const float* x   = (const float*)d_in[0];
    const float* Cw1 = (const float*)d_in[1];
    const float* Cb1 = (const float*)d_in[2];
    const float* Cw2 = (const float*)d_in[3];
    const float* Cb2 = (const float*)d_in[4];
    const float* Nw1 = (const float*)d_in[5];
    const float* Nb1 = (const float*)d_in[6];
    const float* Nw2 = (const float*)d_in[7];
    const float* Nb2 = (const float*)d_in[8];
    const float* Fw1 = (const float*)d_in[9];
    const float* Fb1 = (const float*)d_in[10];
    const float* Fw2 = (const float*)d_in[11];
    const float* Fb2 = (const float*)d_in[12];
    const float* Ow1 = (const float*)d_in[13];
    const float* Ob1 = (const float*)d_in[14];
    const float* Ow2 = (const float*)d_in[15];
    const float* Ob2 = (const float*)d_in[16];
    float* out = (float*)d_out;

    cudaFuncSetAttribute(k_features, cudaFuncAttributeMaxDynamicSharedMemorySize, F_TOT);
    cudaFuncSetAttribute(k_ogemm,    cudaFuncAttributeMaxDynamicSharedMemorySize, OG_TOT);

    const int conv_elems = NB * 8192 + 4 * 8192 + NB * 1024;
    k_convert<<<(conv_elems + 255) / 256, 256>>>(Ow1, Ob1, Ow2, Nw1, Nb1, Nw2,
                                                 Fw1, Fb1, Fw2);

    k_features<<<NTILES, 256, F_TOT>>>(x, Cw1, Cb1, Cw2, Cb2, Nb2, Fb2);

    dim3 grid2(NTILES / 2, 9);
    k_ogemm<<<grid2, 256, OG_TOT>>>(Ob2, out);
}

// round 15
// speedup vs baseline: 1.0888x; 1.0406x over previous
#include <cuda_runtime.h>
#include <cuda_fp16.h>
#include <cstdint>

#define NTILES 512
#define NB     54

// ========================= device scratch (fp16 images) =====================
__device__ __align__(16) __half g_w1h[NB * 8192];  // O_w1: [j=128][k=64], k57=Ob1
__device__ __align__(16) __half g_w2i[NB * 1024];  // O_w2: [n=8][k=128] (n<3 live)
__device__ __align__(16) __half g_bn1[8192];       // N_w1
__device__ __align__(16) __half g_bn2[8192];       // N_w2
__device__ __align__(16) __half g_bf1[8192];       // F_w1
__device__ __align__(16) __half g_bf2[8192];       // F_w2
__device__ __align__(16) __half g_fimg[NTILES * 8192]; // f images (swizzled, col57=1)

// ============================= PTX helpers =================================
__device__ __forceinline__ uint32_t smem_u32(const void* p) {
    uint32_t a;
    asm("{ .reg .u64 t; cvta.to.shared.u64 t, %1; cvt.u32.u64 %0, t; }"
        : "=r"(a) : "l"(p));
    return a;
}
__device__ __forceinline__ void ldsm_x4(uint32_t addr, uint32_t& r0, uint32_t& r1,
                                        uint32_t& r2, uint32_t& r3) {
    asm volatile("ldmatrix.sync.aligned.m8n8.x4.shared.b16 {%0,%1,%2,%3}, [%4];"
                 : "=r"(r0), "=r"(r1), "=r"(r2), "=r"(r3) : "r"(addr));
}
__device__ __forceinline__ void mma16816(float& d0, float& d1, float& d2, float& d3,
                                         uint32_t a0, uint32_t a1, uint32_t a2, uint32_t a3,
                                         uint32_t b0, uint32_t b1) {
    asm volatile("mma.sync.aligned.m16n8k16.row.col.f32.f16.f16.f32 "
                 "{%0,%1,%2,%3}, {%4,%5,%6,%7}, {%8,%9}, {%0,%1,%2,%3};"
                 : "+f"(d0), "+f"(d1), "+f"(d2), "+f"(d3)
                 : "r"(a0), "r"(a1), "r"(a2), "r"(a3), "r"(b0), "r"(b1));
}
__device__ __forceinline__ uint32_t sw128(uint32_t off) {
    return off ^ ((off >> 3) & 0x70);
}
__device__ __forceinline__ uint32_t packh2(float lo, float hi) {
    __half2 h = __floats2half2_rn(lo, hi);
    return *reinterpret_cast<uint32_t*>(&h);
}

// ============================================================================
// Convert weights -> swizzled fp16 images (biases baked at constant-1 k-col).
// ============================================================================
__global__ __launch_bounds__(256) void k_convert(
    const float* __restrict__ Ow1, const float* __restrict__ Ob1,
    const float* __restrict__ Ow2,
    const float* __restrict__ Nw1, const float* __restrict__ Nb1,
    const float* __restrict__ Nw2,
    const float* __restrict__ Fw1, const float* __restrict__ Fb1,
    const float* __restrict__ Fw2)
{
    int idx = blockIdx.x * 256 + threadIdx.x;
    if (idx < NB * 8192) {
        int j = idx & 127, k = (idx >> 7) & 63, n = idx >> 13;
        float v = (k < 57) ? Ow1[n * 7296 + k * 128 + j]
                 : (k == 57 ? Ob1[n * 128 + j] : 0.f);
        g_w1h[n * 8192 + (sw128((unsigned)(j * 128 + k * 2)) >> 1)] = __float2half(v);
        return;
    }
    int t = idx - NB * 8192;
    if (t < 4 * 8192) {
        int img = t >> 13, e = t & 8191;
        if (img == 0) {
            int j = e >> 6, k = e & 63;
            float v = (k < 54) ? Nw1[k * 128 + j] : (k == 54 ? Nb1[j] : 0.f);
            g_bn1[sw128((unsigned)(j * 128 + k * 2)) >> 1] = __float2half(v);
        } else if (img == 1) {
            int j = e >> 6, k = e & 63;
            float v = (k < 57) ? Fw1[k * 128 + j] : (k == 57 ? Fb1[j] : 0.f);
            g_bf1[sw128((unsigned)(j * 128 + k * 2)) >> 1] = __float2half(v);
        } else if (img == 2) {
            int m = e >> 7, k = e & 127;
            float v = (m < 54) ? Nw2[k * 54 + m] : 0.f;
            g_bn2[sw128((unsigned)(m * 256 + k * 2)) >> 1] = __float2half(v);
        } else {
            int m = e >> 7, k = e & 127;
            float v = (m < 57) ? Fw2[k * 57 + m] : 0.f;
            g_bf2[sw128((unsigned)(m * 256 + k * 2)) >> 1] = __float2half(v);
        }
        return;
    }
    t -= 4 * 8192;
    if (t >= NB * 1024) return;
    {
        int n = t >> 10, e = t & 1023;
        int m = e >> 7, k = e & 127;
        float v = (m < 3) ? Ow2[n * 384 + k * 3 + m] : 0.f;
        g_w2i[n * 1024 + (sw128((unsigned)(m * 256 + k * 2)) >> 1)] = __float2half(v);
    }
}

// ==================== features-kernel SMEM layout (91.2 KB, 2 CTAs/SM) ======
#define FX    0
#define FWA   16384
#define FWB   32768
#define FH0   49152
#define FH1   65536
#define FXC   81920
#define FCW1  83968
#define FCW2  86016
#define FCB1  88064
#define FCB2  88576
#define FBN2  88608
#define FBF2  88864
#define FCP   89120
#define F_TOT 91168

// ---- 8-warp layer: 64-K HMMA, 128 out cols, relu (bias baked) -> H0/H1 -----
__device__ __forceinline__ void layer_wide8(
    uint32_t sA, uint32_t sB, char* h0, char* h1, int wid, int lane)
{
    const int m01 = (lane >> 3) & 1, kh = lane >> 4;
    const int quad = lane & 3, qrow = lane >> 2;
    const int bjrow = lane & 7, bkt = lane >> 4, bkh = (lane >> 3) & 1;
    const int rg = wid * 16 + (lane & 7) + (m01 << 3);

    uint32_t a[4][4];
#pragma unroll
    for (int kt = 0; kt < 4; ++kt) {
        uint32_t off = sw128((uint32_t)(rg * 128 + kt * 32 + kh * 16));
        ldsm_x4(sA + off, a[kt][0], a[kt][1], a[kt][2], a[kt][3]);
    }
#pragma unroll 4
    for (int nt = 0; nt < 16; ++nt) {
        uint32_t off0 = sw128((uint32_t)((nt * 8 + bjrow) * 128 + bkt * 32 + bkh * 16));
        uint32_t off1 = sw128((uint32_t)((nt * 8 + bjrow) * 128 + (bkt + 2) * 32 + bkh * 16));
        uint32_t b[4][2];
        ldsm_x4(sB + off0, b[0][0], b[0][1], b[1][0], b[1][1]);
        ldsm_x4(sB + off1, b[2][0], b[2][1], b[3][0], b[3][1]);
        float d0 = 0.f, d1 = 0.f, d2 = 0.f, d3 = 0.f;
#pragma unroll
        for (int kt = 0; kt < 4; ++kt)
            mma16816(d0, d1, d2, d3, a[kt][0], a[kt][1], a[kt][2], a[kt][3],
                     b[kt][0], b[kt][1]);
        int j0 = nt * 8 + quad * 2;
        char* himg = (j0 < 64) ? h0 : h1;
        int   jc   = j0 & 63;
        int rA = wid * 16 + qrow, rB = rA + 8;
        *(__half2*)(himg + sw128((uint32_t)(rA * 128 + jc * 2))) =
            __floats2half2_rn(fmaxf(d0, 0.f), fmaxf(d1, 0.f));
        *(__half2*)(himg + sw128((uint32_t)(rB * 128 + jc * 2))) =
            __floats2half2_rn(fmaxf(d2, 0.f), fmaxf(d3, 0.f));
    }
}

// ---- 8-warp layer: 128-K HMMA (H halves), bias, fp16 -> outimg -------------
__device__ __forceinline__ void layer_narrow8(
    uint32_t sH0, uint32_t sH1, uint32_t sB, const float* __restrict__ bias,
    char* outimg, int coff, int mlim, int ntn, int wid, int lane)
{
    const int m01 = (lane >> 3) & 1, kh = lane >> 4;
    const int quad = lane & 3, qrow = lane >> 2;
    const int bjrow = lane & 7, bkt = lane >> 4, bkh = (lane >> 3) & 1;
    const int rg = wid * 16 + (lane & 7) + (m01 << 3);

    uint32_t a[8][4];
#pragma unroll
    for (int kt = 0; kt < 8; ++kt) {
        uint32_t src = (kt < 4) ? sH0 : sH1;
        int      ktl = kt & 3;
        uint32_t off = sw128((uint32_t)(rg * 128 + ktl * 32 + kh * 16));
        ldsm_x4(src + off, a[kt][0], a[kt][1], a[kt][2], a[kt][3]);
    }
    for (int nt = 0; nt < ntn; ++nt) {
        uint32_t b[8][2];
#pragma unroll
        for (int q = 0; q < 4; ++q) {
            uint32_t off = sw128((uint32_t)((nt * 8 + bjrow) * 256 + q * 64 + bkt * 32 + bkh * 16));
            ldsm_x4(sB + off, b[2 * q][0], b[2 * q][1], b[2 * q + 1][0], b[2 * q + 1][1]);
        }
        float d0 = 0.f, d1 = 0.f, d2 = 0.f, d3 = 0.f;
#pragma unroll
        for (int kt = 0; kt < 8; ++kt)
            mma16816(d0, d1, d2, d3, a[kt][0], a[kt][1], a[kt][2], a[kt][3],
                     b[kt][0], b[kt][1]);
        int m0 = nt * 8 + quad * 2, m1 = m0 + 1;
        int rA = wid * 16 + qrow, rB = rA + 8;
        if (m0 < mlim) {
            *(__half*)(outimg + sw128((uint32_t)(rA * 128 + (m0 + coff) * 2))) =
                __float2half(d0 + bias[m0]);
            *(__half*)(outimg + sw128((uint32_t)(rB * 128 + (m0 + coff) * 2))) =
                __float2half(d2 + bias[m0]);
        }
        if (m1 < mlim) {
            *(__half*)(outimg + sw128((uint32_t)(rA * 128 + (m1 + coff) * 2))) =
                __float2half(d1 + bias[m1]);
            *(__half*)(outimg + sw128((uint32_t)(rB * 128 + (m1 + coff) * 2))) =
                __float2half(d3 + bias[m1]);
        }
    }
}

__device__ __forceinline__ void softmax_store(float* __restrict__ out,
                                              size_t row, int n,
                                              float l0, float l1, float l2)
{
    float mx = fmaxf(l0, fmaxf(l1, l2));
    float e0 = __expf(l0 - mx), e1 = __expf(l1 - mx), e2 = __expf(l2 - mx);
    float inv = 1.f / (e0 + e1 + e2);
    float* o = out + row * 162 + n * 3;
    o[0] = e0 * inv; o[1] = e1 * inv; o[2] = e2 * inv;
}

// ============================================================================
// Kernel 1: features, 256 threads / 8 warps, 128 rows (R12, unchanged).
// ============================================================================
__global__ void __launch_bounds__(256, 2) k_features(
    const float* __restrict__ x,
    const float* __restrict__ Cw1, const float* __restrict__ Cb1v,
    const float* __restrict__ Cw2, const float* __restrict__ Cb2v,
    const float* __restrict__ Nb2v, const float* __restrict__ Fb2v)
{
    extern __shared__ char smem[];
    const uint32_t sbase = smem_u32(smem);
    float* xc   = (float*)(smem + FXC);
    float* cw1t = (float*)(smem + FCW1);
    float* cw2  = (float*)(smem + FCW2);
    float* cb1  = (float*)(smem + FCB1);
    float* cb2  = (float*)(smem + FCB2);
    float* bn2  = (float*)(smem + FBN2);
    float* bf2  = (float*)(smem + FBF2);
    float* cp   = (float*)(smem + FCP);

    const int tid  = threadIdx.x;
    const int wid  = tid >> 5;
    const int lane = tid & 31;
    const int row0 = blockIdx.x * 128;

    for (int i = tid; i < 128 * 58; i += 256) {
        int r = i / 58, c = i - r * 58;
        float v = x[(size_t)(row0 + r) * 58 + c];
        if (c < 4) xc[r * 4 + c] = v;
        else *(__half*)(smem + FX + sw128((uint32_t)(r * 128 + (c - 4) * 2))) =
                 __float2half(v);
    }
    for (int i = tid; i < 128 * 10; i += 256) {
        int r = i / 10, kk = 54 + (i - (i / 10) * 10);
        float v = (kk == 54 || kk == 57) ? 1.f : 0.f;
        *(__half*)(smem + FX + sw128((uint32_t)(r * 128 + kk * 2))) = __float2half(v);
    }
    {
        const uint4* sa = (const uint4*)g_bn1; uint4* da = (uint4*)(smem + FWA);
        const uint4* sb = (const uint4*)g_bn2; uint4* db = (uint4*)(smem + FWB);
#pragma unroll
        for (int i = 0; i < 4; ++i) {
            da[tid + 256 * i] = sa[tid + 256 * i];
            db[tid + 256 * i] = sb[tid + 256 * i];
        }
    }
    if (tid < 128) cb1[tid] = Cb1v[tid];
    else if (tid < 192) {
        int t = tid - 128;
        bn2[t] = (t < 54) ? Nb2v[t] : 0.f;
        bf2[t] = (t < 57) ? Fb2v[t] : 0.f;
    } else if (tid < 196) {
        int t = tid - 192;
        cb2[t] = (t < 3) ? Cb2v[t] : 0.f;
    }
    for (int i = tid; i < 512; i += 256) { int k = i >> 7, j = i & 127; cw1t[j * 4 + k] = Cw1[i]; }
    for (int i = tid; i < 384; i += 256) { int j = i / 3, m = i - j * 3; cw2[j * 4 + m] = Cw2[i]; }
    __syncthreads();

    const int crow = tid & 127, cjh = tid >> 7;
    float c0, c1, c2;
    {
        float cx0 = xc[crow * 4 + 0], cx1 = xc[crow * 4 + 1];
        float cx2 = xc[crow * 4 + 2], cx3 = xc[crow * 4 + 3];
        c0 = cjh ? 0.f : cb2[0];
        c1 = cjh ? 0.f : cb2[1];
        c2 = cjh ? 0.f : cb2[2];
        const int j0 = cjh * 64;
        for (int j = j0; j < j0 + 64; ++j) {
            const float* w = &cw1t[j * 4];
            float h = cb1[j] + cx0 * w[0] + cx1 * w[1] + cx2 * w[2] + cx3 * w[3];
            h = fmaxf(h, 0.f);
            const float* w2 = &cw2[j * 4];
            c0 += h * w2[0]; c1 += h * w2[1]; c2 += h * w2[2];
        }
        if (cjh) {
            cp[crow * 4 + 0] = c0; cp[crow * 4 + 1] = c1; cp[crow * 4 + 2] = c2;
        }
    }

    layer_wide8(sbase + FX, sbase + FWA, smem + FH0, smem + FH1, wid, lane);
    __syncthreads();

    {
        const uint4* s = (const uint4*)g_bf1; uint4* d = (uint4*)(smem + FWA);
#pragma unroll
        for (int i = 0; i < 4; ++i) d[tid + 256 * i] = s[tid + 256 * i];
    }
    layer_narrow8(sbase + FH0, sbase + FH1, sbase + FWB, bn2,
                  smem + FX, 3, 54, 7, wid, lane);
    if (!cjh) {
        float f0 = c0 + cp[crow * 4 + 0];
        float f1 = c1 + cp[crow * 4 + 1];
        float f2 = c2 + cp[crow * 4 + 2];
        *(__half*)(smem + FX + sw128((uint32_t)(crow * 128 + 0))) = __float2half(f0);
        *(__half*)(smem + FX + sw128((uint32_t)(crow * 128 + 2))) = __float2half(f1);
        *(__half*)(smem + FX + sw128((uint32_t)(crow * 128 + 4))) = __float2half(f2);
    }
    __syncthreads();

    {
        const uint4* s = (const uint4*)g_bf2; uint4* d = (uint4*)(smem + FWB);
#pragma unroll
        for (int i = 0; i < 4; ++i) d[tid + 256 * i] = s[tid + 256 * i];
    }
    layer_wide8(sbase + FX, sbase + FWA, smem + FH0, smem + FH1, wid, lane);
    __syncthreads();

    layer_narrow8(sbase + FH0, sbase + FH1, sbase + FWB, bf2,
                  smem + FX, 0, 57, 8, wid, lane);
    __syncthreads();

    {
        const uint4* s = (const uint4*)(smem + FX);
        uint4* d = (uint4*)(g_fimg + (size_t)blockIdx.x * 8192);
#pragma unroll
        for (int i = 0; i < 4; ++i) d[tid + 256 * i] = s[tid + 256 * i];
    }
}

// ==================== O-kernel SMEM layout (106.5 KB, 2 CTAs/SM) ============
#define OG_A    0          // 32 KB: two A tile images (256 rows)
#define OG_B0   32768      // 32 KB: pairbuf0 (branches P,Q contiguous)
#define OG_B2   65536      // 32 KB: pairbuf1
#define OG_W2S  98304      // 8 KB
#define OG_TOT  106496

#define OG_CTAS 288        // persistent: 288 CTAs x 24 pairs = 6912 = 256*9*3

// ============================================================================
// Kernel 2: O stage, PERSISTENT. 256 threads / 8 warps / 256 rows per tile.
// Each CTA walks 24 consecutive branch-pairs in (tile, group, pair) order:
// A tile image + fragments reused across pairs (<=1 tile change per CTA).
// Inner compute loop identical to R12 (223.3 us best).
// ============================================================================
__global__ void __launch_bounds__(256, 2) k_ogemm(
    const float* __restrict__ Ob2, float* __restrict__ out)
{
    extern __shared__ char smem[];
    const uint32_t sbase = smem_u32(smem);

    const int tid  = threadIdx.x;
    const int wid  = tid >> 5;
    const int lane = tid & 31;

    // walk state: pair index space q in [0,24); global item = tile*9+group
    const int qbase = blockIdx.x * 24;
    int item  = qbase / 3;           // qbase divisible by 3
    int pl    = 0;
    int tile  = item / 9;
    int group = item - tile * 9;

    const int quad = lane & 3;
    const int qrow = lane >> 2;
    const int bjrow = lane & 7;
    const int bkt   = lane >> 4;
    const int bkh   = (lane >> 3) & 1;
    const uint32_t w2rowb = (uint32_t)((lane & 7) * 256 + (lane >> 3) * 16);
    const int m01 = (lane >> 3) & 1, kh = lane >> 4;

    // ---- prologue: A image (tile), B pair q=0, W2 q=0 ----------------------
    {
        const uint4* sa = (const uint4*)(g_fimg + (size_t)tile * 16384);
        uint4* dx = (uint4*)(smem + OG_A);
#pragma unroll
        for (int i = 0; i < 8; ++i) dx[tid + 256 * i] = sa[tid + 256 * i];
        int nP0 = group * 6;         // pl = 0
        const uint4* s0 = (const uint4*)(g_w1h + nP0 * 8192);
        uint4* d0 = (uint4*)(smem + OG_B0);
#pragma unroll
        for (int i = 0; i < 8; ++i) d0[tid + 256 * i] = s0[tid + 256 * i];
        ((uint4*)(smem + OG_W2S))[tid] = ((const uint4*)(g_w2i + nP0 * 1024))[tid];
    }
    __syncthreads();

    // ---- A fragments for current tile --------------------------------------
    uint32_t a[2][4][4];
#pragma unroll
    for (int mt = 0; mt < 2; ++mt) {
        int rg = wid * 32 + mt * 16 + (lane & 7) + (m01 << 3);
        uint32_t base = sbase + OG_A + (uint32_t)(rg >> 7) * 16384;
        int rl = rg & 127;
#pragma unroll
        for (int kt = 0; kt < 4; ++kt) {
            uint32_t off = sw128((uint32_t)(rl * 128 + kt * 32 + kh * 16));
            ldsm_x4(base + off,
                    a[mt][kt][0], a[mt][kt][1], a[mt][kt][2], a[mt][kt][3]);
        }
    }
    __syncthreads();   // all frags built before any future A-image overwrite

    int frag_tile = tile;

    for (int q = 0; q < 24; ++q) {
        const int buf = q & 1, nxt = buf ^ 1;
        const int nP = group * 6 + pl * 2, nQ = nP + 1;
        const int row0 = tile * 256;

        // rebuild A fragments if the tile advanced (image already prefetched)
        if (tile != frag_tile) {
#pragma unroll
            for (int mt = 0; mt < 2; ++mt) {
                int rg = wid * 32 + mt * 16 + (lane & 7) + (m01 << 3);
                uint32_t base = sbase + OG_A + (uint32_t)(rg >> 7) * 16384;
                int rl = rg & 127;
#pragma unroll
                for (int kt = 0; kt < 4; ++kt) {
                    uint32_t off = sw128((uint32_t)(rl * 128 + kt * 32 + kh * 16));
                    ldsm_x4(base + off,
                            a[mt][kt][0], a[mt][kt][1], a[mt][kt][2], a[mt][kt][3]);
                }
            }
            frag_tile = tile;
            __syncthreads();
        }

        // compute next-pair indices and prefetch (B pair, W2, maybe A image)
        int npl = pl + 1, ngroup = group, ntile = tile;
        if (npl == 3) { npl = 0; ++ngroup; if (ngroup == 9) { ngroup = 0; ++ntile; } }
        if (q < 23) {
            int nPn = ngroup * 6 + npl * 2;
            const uint4* s0 = (const uint4*)(g_w1h + nPn * 8192);
            uint4* d0 = (uint4*)(smem + (nxt ? OG_B2 : OG_B0));
#pragma unroll
            for (int i = 0; i < 8; ++i) d0[tid + 256 * i] = s0[tid + 256 * i];
            ((uint4*)(smem + OG_W2S + nxt * 4096))[tid] =
                ((const uint4*)(g_w2i + nPn * 1024))[tid];
            if (ntile != tile) {      // safe: frags built & sync'd above
                const uint4* sa = (const uint4*)(g_fimg + (size_t)ntile * 16384);
                uint4* dx = (uint4*)(smem + OG_A);
#pragma unroll
                for (int i = 0; i < 8; ++i) dx[tid + 256 * i] = sa[tid + 256 * i];
            }
        }

        const uint32_t sb0  = sbase + (buf ? OG_B2 : OG_B0);
        const uint32_t sb1  = sb0 + 16384;
        const uint32_t sw2P = sbase + OG_W2S + (uint32_t)buf * 4096;
        const uint32_t sw2Q = sw2P + 2048;

        float lgP[2][4], lgQ[2][4];
        {
            int cc0 = 2 * quad, cc1 = cc0 + 1;
            float p0 = (cc0 < 3) ? Ob2[nP * 3 + cc0] : 0.f;
            float p1 = (cc1 < 3) ? Ob2[nP * 3 + cc1] : 0.f;
            float q0 = (cc0 < 3) ? Ob2[nQ * 3 + cc0] : 0.f;
            float q1 = (cc1 < 3) ? Ob2[nQ * 3 + cc1] : 0.f;
#pragma unroll
            for (int mt = 0; mt < 2; ++mt) {
                lgP[mt][0] = p0; lgP[mt][1] = p1; lgP[mt][2] = p0; lgP[mt][3] = p1;
                lgQ[mt][0] = q0; lgQ[mt][1] = q1; lgQ[mt][2] = q0; lgQ[mt][3] = q1;
            }
        }

        uint32_t b2P[2][2], b2Q[2][2];
#pragma unroll
        for (int kt = 0; kt < 8; ++kt) {
            if ((kt & 1) == 0) {
                uint32_t off = sw128(w2rowb + (uint32_t)(kt >> 1) * 64);
                ldsm_x4(sw2P + off, b2P[0][0], b2P[0][1], b2P[1][0], b2P[1][1]);
                ldsm_x4(sw2Q + off, b2Q[0][0], b2Q[0][1], b2Q[1][0], b2Q[1][1]);
            }
            uint32_t a2P[2][4], a2Q[2][4];
#pragma unroll
            for (int e = 0; e < 2; ++e) {
                const int nt = 2 * kt + e;
                uint32_t off0 = sw128((uint32_t)((nt * 8 + bjrow) * 128 + bkt * 32 + bkh * 16));
                uint32_t off1 = sw128((uint32_t)((nt * 8 + bjrow) * 128 + (bkt + 2) * 32 + bkh * 16));
                uint32_t bP[4][2], bQ[4][2];
                ldsm_x4(sb0 + off0, bP[0][0], bP[0][1], bP[1][0], bP[1][1]);
                ldsm_x4(sb0 + off1, bP[2][0], bP[2][1], bP[3][0], bP[3][1]);
                ldsm_x4(sb1 + off0, bQ[0][0], bQ[0][1], bQ[1][0], bQ[1][1]);
                ldsm_x4(sb1 + off1, bQ[2][0], bQ[2][1], bQ[3][0], bQ[3][1]);
#pragma unroll
                for (int mt = 0; mt < 2; ++mt) {
                    float dP0 = 0.f, dP1 = 0.f, dP2 = 0.f, dP3 = 0.f;
                    float dQ0 = 0.f, dQ1 = 0.f, dQ2 = 0.f, dQ3 = 0.f;
#pragma unroll
                    for (int k4 = 0; k4 < 4; ++k4) {
                        mma16816(dP0, dP1, dP2, dP3,
                                 a[mt][k4][0], a[mt][k4][1], a[mt][k4][2], a[mt][k4][3],
                                 bP[k4][0], bP[k4][1]);
                        mma16816(dQ0, dQ1, dQ2, dQ3,
                                 a[mt][k4][0], a[mt][k4][1], a[mt][k4][2], a[mt][k4][3],
                                 bQ[k4][0], bQ[k4][1]);
                    }
                    a2P[mt][2 * e]     = packh2(fmaxf(dP0, 0.f), fmaxf(dP1, 0.f));
                    a2P[mt][2 * e + 1] = packh2(fmaxf(dP2, 0.f), fmaxf(dP3, 0.f));
                    a2Q[mt][2 * e]     = packh2(fmaxf(dQ0, 0.f), fmaxf(dQ1, 0.f));
                    a2Q[mt][2 * e + 1] = packh2(fmaxf(dQ2, 0.f), fmaxf(dQ3, 0.f));
                }
            }
#pragma unroll
            for (int mt = 0; mt < 2; ++mt) {
                mma16816(lgP[mt][0], lgP[mt][1], lgP[mt][2], lgP[mt][3],
                         a2P[mt][0], a2P[mt][1], a2P[mt][2], a2P[mt][3],
                         b2P[kt & 1][0], b2P[kt & 1][1]);
                mma16816(lgQ[mt][0], lgQ[mt][1], lgQ[mt][2], lgQ[mt][3],
                         a2Q[mt][0], a2Q[mt][1], a2Q[mt][2], a2Q[mt][3],
                         b2Q[kt & 1][0], b2Q[kt & 1][1]);
            }
        }

#pragma unroll
        for (int mt = 0; mt < 2; ++mt) {
            float tP0 = __shfl_xor_sync(0xffffffffu, lgP[mt][0], 1);
            float tP2 = __shfl_xor_sync(0xffffffffu, lgP[mt][2], 1);
            float tQ0 = __shfl_xor_sync(0xffffffffu, lgQ[mt][0], 1);
            float tQ2 = __shfl_xor_sync(0xffffffffu, lgQ[mt][2], 1);
            if (quad == 0) {
                size_t rA = (size_t)(row0 + wid * 32 + mt * 16 + qrow);
                size_t rB = rA + 8;
                softmax_store(out, rA, nP, lgP[mt][0], lgP[mt][1], tP0);
                softmax_store(out, rB, nP, lgP[mt][2], lgP[mt][3], tP2);
                softmax_store(out, rA, nQ, lgQ[mt][0], lgQ[mt][1], tQ0);
                softmax_store(out, rB, nQ, lgQ[mt][2], lgQ[mt][3], tQ2);
            }
        }
        __syncthreads();

        pl = npl; group = ngroup; tile = ntile;
    }
}

// ============================================================================
extern "C" void kernel_launch(void* const* d_in, const int* in_sizes, int n_in,
                              void* d_out, int out_size)
{
    const float* x   = (const float*)d_in[0];
    const float* Cw1 = (const float*)d_in[1];
    const float* Cb1 = (const float*)d_in[2];
    const float* Cw2 = (const float*)d_in[3];
    const float* Cb2 = (const float*)d_in[4];
    const float* Nw1 = (const float*)d_in[5];
    const float* Nb1 = (const float*)d_in[6];
    const float* Nw2 = (const float*)d_in[7];
    const float* Nb2 = (const float*)d_in[8];
    const float* Fw1 = (const float*)d_in[9];
    const float* Fb1 = (const float*)d_in[10];
    const float* Fw2 = (const float*)d_in[11];
    const float* Fb2 = (const float*)d_in[12];
    const float* Ow1 = (const float*)d_in[13];
    const float* Ob1 = (const float*)d_in[14];
    const float* Ow2 = (const float*)d_in[15];
    const float* Ob2 = (const float*)d_in[16];
    float* out = (float*)d_out;

    cudaFuncSetAttribute(k_features, cudaFuncAttributeMaxDynamicSharedMemorySize, F_TOT);
    cudaFuncSetAttribute(k_ogemm,    cudaFuncAttributeMaxDynamicSharedMemorySize, OG_TOT);

    const int conv_elems = NB * 8192 + 4 * 8192 + NB * 1024;
    k_convert<<<(conv_elems + 255) / 256, 256>>>(Ow1, Ob1, Ow2, Nw1, Nb1, Nw2,
                                                 Fw1, Fb1, Fw2);

    k_features<<<NTILES, 256, F_TOT>>>(x, Cw1, Cb1, Cw2, Cb2, Nb2, Fb2);

    k_ogemm<<<OG_CTAS, 256, OG_TOT>>>(Ob2, out);
}

// round 16
// speedup vs baseline: 1.1478x; 1.0542x over previous
#include <cuda_runtime.h>
#include <cuda_fp16.h>
#include <cstdint>

#define NTILES 512
#define NB     54

// ========================= device scratch (fp16 images) =====================
__device__ __align__(16) __half g_w1h[NB * 8192];  // O_w1: [j=128][k=64], k57=Ob1
__device__ __align__(16) __half g_w2i[NB * 1024];  // O_w2: [n=8][k=128] (n<3 live)
__device__ __align__(16) __half g_bn1[8192];       // N_w1
__device__ __align__(16) __half g_bn2[8192];       // N_w2
__device__ __align__(16) __half g_bf1[8192];       // F_w1
__device__ __align__(16) __half g_bf2[8192];       // F_w2
__device__ __align__(16) __half g_fimg[NTILES * 8192]; // f images (swizzled, col57=1)

// ============================= PTX helpers =================================
__device__ __forceinline__ uint32_t smem_u32(const void* p) {
    uint32_t a;
    asm("{ .reg .u64 t; cvta.to.shared.u64 t, %1; cvt.u32.u64 %0, t; }"
        : "=r"(a) : "l"(p));
    return a;
}
__device__ __forceinline__ void ldsm_x4(uint32_t addr, uint32_t& r0, uint32_t& r1,
                                        uint32_t& r2, uint32_t& r3) {
    asm volatile("ldmatrix.sync.aligned.m8n8.x4.shared.b16 {%0,%1,%2,%3}, [%4];"
                 : "=r"(r0), "=r"(r1), "=r"(r2), "=r"(r3) : "r"(addr));
}
__device__ __forceinline__ void mma16816(float& d0, float& d1, float& d2, float& d3,
                                         uint32_t a0, uint32_t a1, uint32_t a2, uint32_t a3,
                                         uint32_t b0, uint32_t b1) {
    asm volatile("mma.sync.aligned.m16n8k16.row.col.f32.f16.f16.f32 "
                 "{%0,%1,%2,%3}, {%4,%5,%6,%7}, {%8,%9}, {%0,%1,%2,%3};"
                 : "+f"(d0), "+f"(d1), "+f"(d2), "+f"(d3)
                 : "r"(a0), "r"(a1), "r"(a2), "r"(a3), "r"(b0), "r"(b1));
}
__device__ __forceinline__ uint32_t sw128(uint32_t off) {
    return off ^ ((off >> 3) & 0x70);
}
__device__ __forceinline__ uint32_t packh2(float lo, float hi) {
    __half2 h = __floats2half2_rn(lo, hi);
    return *reinterpret_cast<uint32_t*>(&h);
}
#define CP_ASYNC16(dst, src) \
    asm volatile("cp.async.cg.shared.global [%0], [%1], 16;" \
                 :: "r"(dst), "l"(src) : "memory")
#define CP_COMMIT() asm volatile("cp.async.commit_group;" ::: "memory")
#define CP_WAIT0()  asm volatile("cp.async.wait_group 0;"  ::: "memory")

// ============================================================================
// Convert weights -> swizzled fp16 images (biases baked at constant-1 k-col).
// Paired half2 stores: one 4-byte store per thread-item (k-pairs contiguous
// under sw128, which only permutes bits [4:6]).
// ============================================================================
__global__ __launch_bounds__(256) void k_convert(
    const float* __restrict__ Ow1, const float* __restrict__ Ob1,
    const float* __restrict__ Ow2,
    const float* __restrict__ Nw1, const float* __restrict__ Nb1,
    const float* __restrict__ Nw2,
    const float* __restrict__ Fw1, const float* __restrict__ Fb1,
    const float* __restrict__ Fw2)
{
    int idx = blockIdx.x * 256 + threadIdx.x;
    const int OW1P = NB * 4096;
    if (idx < OW1P) {                       // O_w1 images: [j=128][k=64]
        int kp = idx & 31, j = (idx >> 5) & 127, n = idx >> 12;
        int k0 = kp * 2, k1 = k0 + 1;
        float v0 = (k0 < 57) ? Ow1[n * 7296 + k0 * 128 + j]
                 : (k0 == 57 ? Ob1[n * 128 + j] : 0.f);
        float v1 = (k1 < 57) ? Ow1[n * 7296 + k1 * 128 + j]
                 : (k1 == 57 ? Ob1[n * 128 + j] : 0.f);
        *(__half2*)((char*)g_w1h + n * 16384 + sw128((unsigned)(j * 128 + k0 * 2))) =
            __floats2half2_rn(v0, v1);
        return;
    }
    int t = idx - OW1P;
    if (t < 2 * 4096) {                     // N_w1 / F_w1 images
        int img = t >> 12, e = t & 4095;
        int kp = e & 31, j = e >> 5;
        int k0 = kp * 2, k1 = k0 + 1;
        if (img == 0) {
            float v0 = (k0 < 54) ? Nw1[k0 * 128 + j] : (k0 == 54 ? Nb1[j] : 0.f);
            float v1 = (k1 < 54) ? Nw1[k1 * 128 + j] : (k1 == 54 ? Nb1[j] : 0.f);
            *(__half2*)((char*)g_bn1 + sw128((unsigned)(j * 128 + k0 * 2))) =
                __floats2half2_rn(v0, v1);
        } else {
            float v0 = (k0 < 57) ? Fw1[k0 * 128 + j] : (k0 == 57 ? Fb1[j] : 0.f);
            float v1 = (k1 < 57) ? Fw1[k1 * 128 + j] : (k1 == 57 ? Fb1[j] : 0.f);
            *(__half2*)((char*)g_bf1 + sw128((unsigned)(j * 128 + k0 * 2))) =
                __floats2half2_rn(v0, v1);
        }
        return;
    }
    t -= 2 * 4096;
    if (t < 2 * 4096) {                     // N_w2 / F_w2 images: [m=64][k=128]
        int img = t >> 12, e = t & 4095;
        int kp = e & 63, m = e >> 6;
        int k0 = kp * 2, k1 = k0 + 1;
        if (img == 0) {
            float v0 = (m < 54) ? Nw2[k0 * 54 + m] : 0.f;
            float v1 = (m < 54) ? Nw2[k1 * 54 + m] : 0.f;
            *(__half2*)((char*)g_bn2 + sw128((unsigned)(m * 256 + k0 * 2))) =
                __floats2half2_rn(v0, v1);
        } else {
            float v0 = (m < 57) ? Fw2[k0 * 57 + m] : 0.f;
            float v1 = (m < 57) ? Fw2[k1 * 57 + m] : 0.f;
            *(__half2*)((char*)g_bf2 + sw128((unsigned)(m * 256 + k0 * 2))) =
                __floats2half2_rn(v0, v1);
        }
        return;
    }
    t -= 2 * 4096;
    if (t >= NB * 512) return;
    {                                       // O_w2 images: [n=8][k=128]
        int n = t >> 9, e = t & 511;
        int kp = e & 63, m = e >> 6;
        int k0 = kp * 2, k1 = k0 + 1;
        float v0 = (m < 3) ? Ow2[n * 384 + k0 * 3 + m] : 0.f;
        float v1 = (m < 3) ? Ow2[n * 384 + k1 * 3 + m] : 0.f;
        *(__half2*)((char*)g_w2i + n * 2048 + sw128((unsigned)(m * 256 + k0 * 2))) =
            __floats2half2_rn(v0, v1);
    }
}

// ==================== features-kernel SMEM layout (91.2 KB, 2 CTAs/SM) ======
#define FX    0
#define FWA   16384
#define FWB   32768
#define FH0   49152
#define FH1   65536
#define FXC   81920
#define FCW1  83968
#define FCW2  86016
#define FCB1  88064
#define FCB2  88576
#define FBN2  88608
#define FBF2  88864
#define FCP   89120
#define F_TOT 91168

// ---- 8-warp layer: 64-K HMMA, 128 out cols, relu (bias baked) -> H0/H1 -----
__device__ __forceinline__ void layer_wide8(
    uint32_t sA, uint32_t sB, char* h0, char* h1, int wid, int lane)
{
    const int m01 = (lane >> 3) & 1, kh = lane >> 4;
    const int quad = lane & 3, qrow = lane >> 2;
    const int bjrow = lane & 7, bkt = lane >> 4, bkh = (lane >> 3) & 1;
    const int rg = wid * 16 + (lane & 7) + (m01 << 3);

    uint32_t a[4][4];
#pragma unroll
    for (int kt = 0; kt < 4; ++kt) {
        uint32_t off = sw128((uint32_t)(rg * 128 + kt * 32 + kh * 16));
        ldsm_x4(sA + off, a[kt][0], a[kt][1], a[kt][2], a[kt][3]);
    }
#pragma unroll 4
    for (int nt = 0; nt < 16; ++nt) {
        uint32_t off0 = sw128((uint32_t)((nt * 8 + bjrow) * 128 + bkt * 32 + bkh * 16));
        uint32_t off1 = sw128((uint32_t)((nt * 8 + bjrow) * 128 + (bkt + 2) * 32 + bkh * 16));
        uint32_t b[4][2];
        ldsm_x4(sB + off0, b[0][0], b[0][1], b[1][0], b[1][1]);
        ldsm_x4(sB + off1, b[2][0], b[2][1], b[3][0], b[3][1]);
        float d0 = 0.f, d1 = 0.f, d2 = 0.f, d3 = 0.f;
#pragma unroll
        for (int kt = 0; kt < 4; ++kt)
            mma16816(d0, d1, d2, d3, a[kt][0], a[kt][1], a[kt][2], a[kt][3],
                     b[kt][0], b[kt][1]);
        int j0 = nt * 8 + quad * 2;
        char* himg = (j0 < 64) ? h0 : h1;
        int   jc   = j0 & 63;
        int rA = wid * 16 + qrow, rB = rA + 8;
        *(__half2*)(himg + sw128((uint32_t)(rA * 128 + jc * 2))) =
            __floats2half2_rn(fmaxf(d0, 0.f), fmaxf(d1, 0.f));
        *(__half2*)(himg + sw128((uint32_t)(rB * 128 + jc * 2))) =
            __floats2half2_rn(fmaxf(d2, 0.f), fmaxf(d3, 0.f));
    }
}

// ---- 8-warp layer: 128-K HMMA (H halves), bias, fp16 -> outimg -------------
__device__ __forceinline__ void layer_narrow8(
    uint32_t sH0, uint32_t sH1, uint32_t sB, const float* __restrict__ bias,
    char* outimg, int coff, int mlim, int ntn, int wid, int lane)
{
    const int m01 = (lane >> 3) & 1, kh = lane >> 4;
    const int quad = lane & 3, qrow = lane >> 2;
    const int bjrow = lane & 7, bkt = lane >> 4, bkh = (lane >> 3) & 1;
    const int rg = wid * 16 + (lane & 7) + (m01 << 3);

    uint32_t a[8][4];
#pragma unroll
    for (int kt = 0; kt < 8; ++kt) {
        uint32_t src = (kt < 4) ? sH0 : sH1;
        int      ktl = kt & 3;
        uint32_t off = sw128((uint32_t)(rg * 128 + ktl * 32 + kh * 16));
        ldsm_x4(src + off, a[kt][0], a[kt][1], a[kt][2], a[kt][3]);
    }
    for (int nt = 0; nt < ntn; ++nt) {
        uint32_t b[8][2];
#pragma unroll
        for (int q = 0; q < 4; ++q) {
            uint32_t off = sw128((uint32_t)((nt * 8 + bjrow) * 256 + q * 64 + bkt * 32 + bkh * 16));
            ldsm_x4(sB + off, b[2 * q][0], b[2 * q][1], b[2 * q + 1][0], b[2 * q + 1][1]);
        }
        float d0 = 0.f, d1 = 0.f, d2 = 0.f, d3 = 0.f;
#pragma unroll
        for (int kt = 0; kt < 8; ++kt)
            mma16816(d0, d1, d2, d3, a[kt][0], a[kt][1], a[kt][2], a[kt][3],
                     b[kt][0], b[kt][1]);
        int m0 = nt * 8 + quad * 2, m1 = m0 + 1;
        int rA = wid * 16 + qrow, rB = rA + 8;
        if (m0 < mlim) {
            *(__half*)(outimg + sw128((uint32_t)(rA * 128 + (m0 + coff) * 2))) =
                __float2half(d0 + bias[m0]);
            *(__half*)(outimg + sw128((uint32_t)(rB * 128 + (m0 + coff) * 2))) =
                __float2half(d2 + bias[m0]);
        }
        if (m1 < mlim) {
            *(__half*)(outimg + sw128((uint32_t)(rA * 128 + (m1 + coff) * 2))) =
                __float2half(d1 + bias[m1]);
            *(__half*)(outimg + sw128((uint32_t)(rB * 128 + (m1 + coff) * 2))) =
                __float2half(d3 + bias[m1]);
        }
    }
}

__device__ __forceinline__ void softmax_store(float* __restrict__ out,
                                              size_t row, int n,
                                              float l0, float l1, float l2)
{
    float mx = fmaxf(l0, fmaxf(l1, l2));
    float e0 = __expf(l0 - mx), e1 = __expf(l1 - mx), e2 = __expf(l2 - mx);
    float inv = 1.f / (e0 + e1 + e2);
    float* o = out + row * 162 + n * 3;
    o[0] = e0 * inv; o[1] = e1 * inv; o[2] = e2 * inv;
}

// ============================================================================
// Kernel 1: features, 256 threads / 8 warps, 128 rows (R12, unchanged).
// ============================================================================
__global__ void __launch_bounds__(256, 2) k_features(
    const float* __restrict__ x,
    const float* __restrict__ Cw1, const float* __restrict__ Cb1v,
    const float* __restrict__ Cw2, const float* __restrict__ Cb2v,
    const float* __restrict__ Nb2v, const float* __restrict__ Fb2v)
{
    extern __shared__ char smem[];
    const uint32_t sbase = smem_u32(smem);
    float* xc   = (float*)(smem + FXC);
    float* cw1t = (float*)(smem + FCW1);
    float* cw2  = (float*)(smem + FCW2);
    float* cb1  = (float*)(smem + FCB1);
    float* cb2  = (float*)(smem + FCB2);
    float* bn2  = (float*)(smem + FBN2);
    float* bf2  = (float*)(smem + FBF2);
    float* cp   = (float*)(smem + FCP);

    const int tid  = threadIdx.x;
    const int wid  = tid >> 5;
    const int lane = tid & 31;
    const int row0 = blockIdx.x * 128;

    for (int i = tid; i < 128 * 58; i += 256) {
        int r = i / 58, c = i - r * 58;
        float v = x[(size_t)(row0 + r) * 58 + c];
        if (c < 4) xc[r * 4 + c] = v;
        else *(__half*)(smem + FX + sw128((uint32_t)(r * 128 + (c - 4) * 2))) =
                 __float2half(v);
    }
    for (int i = tid; i < 128 * 10; i += 256) {
        int r = i / 10, kk = 54 + (i - (i / 10) * 10);
        float v = (kk == 54 || kk == 57) ? 1.f : 0.f;
        *(__half*)(smem + FX + sw128((uint32_t)(r * 128 + kk * 2))) = __float2half(v);
    }
    {
        const uint4* sa = (const uint4*)g_bn1; uint4* da = (uint4*)(smem + FWA);
        const uint4* sb = (const uint4*)g_bn2; uint4* db = (uint4*)(smem + FWB);
#pragma unroll
        for (int i = 0; i < 4; ++i) {
            da[tid + 256 * i] = sa[tid + 256 * i];
            db[tid + 256 * i] = sb[tid + 256 * i];
        }
    }
    if (tid < 128) cb1[tid] = Cb1v[tid];
    else if (tid < 192) {
        int t = tid - 128;
        bn2[t] = (t < 54) ? Nb2v[t] : 0.f;
        bf2[t] = (t < 57) ? Fb2v[t] : 0.f;
    } else if (tid < 196) {
        int t = tid - 192;
        cb2[t] = (t < 3) ? Cb2v[t] : 0.f;
    }
    for (int i = tid; i < 512; i += 256) { int k = i >> 7, j = i & 127; cw1t[j * 4 + k] = Cw1[i]; }
    for (int i = tid; i < 384; i += 256) { int j = i / 3, m = i - j * 3; cw2[j * 4 + m] = Cw2[i]; }
    __syncthreads();

    const int crow = tid & 127, cjh = tid >> 7;
    float c0, c1, c2;
    {
        float cx0 = xc[crow * 4 + 0], cx1 = xc[crow * 4 + 1];
        float cx2 = xc[crow * 4 + 2], cx3 = xc[crow * 4 + 3];
        c0 = cjh ? 0.f : cb2[0];
        c1 = cjh ? 0.f : cb2[1];
        c2 = cjh ? 0.f : cb2[2];
        const int j0 = cjh * 64;
        for (int j = j0; j < j0 + 64; ++j) {
            const float* w = &cw1t[j * 4];
            float h = cb1[j] + cx0 * w[0] + cx1 * w[1] + cx2 * w[2] + cx3 * w[3];
            h = fmaxf(h, 0.f);
            const float* w2 = &cw2[j * 4];
            c0 += h * w2[0]; c1 += h * w2[1]; c2 += h * w2[2];
        }
        if (cjh) {
            cp[crow * 4 + 0] = c0; cp[crow * 4 + 1] = c1; cp[crow * 4 + 2] = c2;
        }
    }

    layer_wide8(sbase + FX, sbase + FWA, smem + FH0, smem + FH1, wid, lane);
    __syncthreads();

    {
        const uint4* s = (const uint4*)g_bf1; uint4* d = (uint4*)(smem + FWA);
#pragma unroll
        for (int i = 0; i < 4; ++i) d[tid + 256 * i] = s[tid + 256 * i];
    }
    layer_narrow8(sbase + FH0, sbase + FH1, sbase + FWB, bn2,
                  smem + FX, 3, 54, 7, wid, lane);
    if (!cjh) {
        float f0 = c0 + cp[crow * 4 + 0];
        float f1 = c1 + cp[crow * 4 + 1];
        float f2 = c2 + cp[crow * 4 + 2];
        *(__half*)(smem + FX + sw128((uint32_t)(crow * 128 + 0))) = __float2half(f0);
        *(__half*)(smem + FX + sw128((uint32_t)(crow * 128 + 2))) = __float2half(f1);
        *(__half*)(smem + FX + sw128((uint32_t)(crow * 128 + 4))) = __float2half(f2);
    }
    __syncthreads();

    {
        const uint4* s = (const uint4*)g_bf2; uint4* d = (uint4*)(smem + FWB);
#pragma unroll
        for (int i = 0; i < 4; ++i) d[tid + 256 * i] = s[tid + 256 * i];
    }
    layer_wide8(sbase + FX, sbase + FWA, smem + FH0, smem + FH1, wid, lane);
    __syncthreads();

    layer_narrow8(sbase + FH0, sbase + FH1, sbase + FWB, bf2,
                  smem + FX, 0, 57, 8, wid, lane);
    __syncthreads();

    {
        const uint4* s = (const uint4*)(smem + FX);
        uint4* d = (uint4*)(g_fimg + (size_t)blockIdx.x * 8192);
#pragma unroll
        for (int i = 0; i < 4; ++i) d[tid + 256 * i] = s[tid + 256 * i];
    }
}

// ==================== O-kernel SMEM layout (106.5 KB, 2 CTAs/SM) ============
#define OG_A    0          // 32 KB: two A tile images (256 rows)
#define OG_B0   32768      // 32 KB: pairbuf0 (branches P,Q contiguous)
#define OG_B2   65536      // 32 KB: pairbuf1
#define OG_W2S  98304      // 8 KB
#define OG_TOT  106496

#define OG_CTAS 288        // persistent: 288 CTAs x 24 pairs = 6912 = 256*9*3

// ============================================================================
// Kernel 2: O stage, PERSISTENT (R15) + cp.async prefetch (register diet).
// Inner compute loop identical to R12/R15.
// ============================================================================
__global__ void __launch_bounds__(256, 2) k_ogemm(
    const float* __restrict__ Ob2, float* __restrict__ out)
{
    extern __shared__ char smem[];
    const uint32_t sbase = smem_u32(smem);

    const int tid  = threadIdx.x;
    const int wid  = tid >> 5;
    const int lane = tid & 31;

    const int qbase = blockIdx.x * 24;
    int item  = qbase / 3;
    int pl    = 0;
    int tile  = item / 9;
    int group = item - tile * 9;

    const int quad = lane & 3;
    const int qrow = lane >> 2;
    const int bjrow = lane & 7;
    const int bkt   = lane >> 4;
    const int bkh   = (lane >> 3) & 1;
    const uint32_t w2rowb = (uint32_t)((lane & 7) * 256 + (lane >> 3) * 16);
    const int m01 = (lane >> 3) & 1, kh = lane >> 4;

    // ---- prologue: A image (tile), B pair q=0, W2 q=0 (synchronous) --------
    {
        const uint4* sa = (const uint4*)(g_fimg + (size_t)tile * 16384);
        uint4* dx = (uint4*)(smem + OG_A);
#pragma unroll
        for (int i = 0; i < 8; ++i) dx[tid + 256 * i] = sa[tid + 256 * i];
        int nP0 = group * 6;
        const uint4* s0 = (const uint4*)(g_w1h + nP0 * 8192);
        uint4* d0 = (uint4*)(smem + OG_B0);
#pragma unroll
        for (int i = 0; i < 8; ++i) d0[tid + 256 * i] = s0[tid + 256 * i];
        ((uint4*)(smem + OG_W2S))[tid] = ((const uint4*)(g_w2i + nP0 * 1024))[tid];
    }
    __syncthreads();

    uint32_t a[2][4][4];
#pragma unroll
    for (int mt = 0; mt < 2; ++mt) {
        int rg = wid * 32 + mt * 16 + (lane & 7) + (m01 << 3);
        uint32_t base = sbase + OG_A + (uint32_t)(rg >> 7) * 16384;
        int rl = rg & 127;
#pragma unroll
        for (int kt = 0; kt < 4; ++kt) {
            uint32_t off = sw128((uint32_t)(rl * 128 + kt * 32 + kh * 16));
            ldsm_x4(base + off,
                    a[mt][kt][0], a[mt][kt][1], a[mt][kt][2], a[mt][kt][3]);
        }
    }
    __syncthreads();

    int frag_tile = tile;

    for (int q = 0; q < 24; ++q) {
        const int buf = q & 1, nxt = buf ^ 1;
        const int nP = group * 6 + pl * 2, nQ = nP + 1;
        const int row0 = tile * 256;

        if (tile != frag_tile) {
#pragma unroll
            for (int mt = 0; mt < 2; ++mt) {
                int rg = wid * 32 + mt * 16 + (lane & 7) + (m01 << 3);
                uint32_t base = sbase + OG_A + (uint32_t)(rg >> 7) * 16384;
                int rl = rg & 127;
#pragma unroll
                for (int kt = 0; kt < 4; ++kt) {
                    uint32_t off = sw128((uint32_t)(rl * 128 + kt * 32 + kh * 16));
                    ldsm_x4(base + off,
                            a[mt][kt][0], a[mt][kt][1], a[mt][kt][2], a[mt][kt][3]);
                }
            }
            frag_tile = tile;
            __syncthreads();
        }

        // next-pair indices + async prefetch (no register carriers)
        int npl = pl + 1, ngroup = group, ntile = tile;
        if (npl == 3) { npl = 0; ++ngroup; if (ngroup == 9) { ngroup = 0; ++ntile; } }
        if (q < 23) {
            int nPn = ngroup * 6 + npl * 2;
            uint32_t db = sbase + (nxt ? OG_B2 : OG_B0);
            const char* sg = (const char*)(g_w1h + nPn * 8192);
#pragma unroll
            for (int i = 0; i < 8; ++i) {
                uint32_t o = (uint32_t)(tid + 256 * i) * 16;
                CP_ASYNC16(db + o, sg + o);
            }
            CP_ASYNC16(sbase + OG_W2S + (uint32_t)nxt * 4096 + (uint32_t)tid * 16,
                       (const char*)(g_w2i + nPn * 1024) + tid * 16);
            if (ntile != tile) {      // safe: frags built & sync'd above
                const char* sa = (const char*)(g_fimg + (size_t)ntile * 16384);
#pragma unroll
                for (int i = 0; i < 8; ++i) {
                    uint32_t o = (uint32_t)(tid + 256 * i) * 16;
                    CP_ASYNC16(sbase + OG_A + o, sa + o);
                }
            }
            CP_COMMIT();
        }

        const uint32_t sb0  = sbase + (buf ? OG_B2 : OG_B0);
        const uint32_t sb1  = sb0 + 16384;
        const uint32_t sw2P = sbase + OG_W2S + (uint32_t)buf * 4096;
        const uint32_t sw2Q = sw2P + 2048;

        float lgP[2][4], lgQ[2][4];
        {
            int cc0 = 2 * quad, cc1 = cc0 + 1;
            float p0 = (cc0 < 3) ? Ob2[nP * 3 + cc0] : 0.f;
            float p1 = (cc1 < 3) ? Ob2[nP * 3 + cc1] : 0.f;
            float q0 = (cc0 < 3) ? Ob2[nQ * 3 + cc0] : 0.f;
            float q1 = (cc1 < 3) ? Ob2[nQ * 3 + cc1] : 0.f;
#pragma unroll
            for (int mt = 0; mt < 2; ++mt) {
                lgP[mt][0] = p0; lgP[mt][1] = p1; lgP[mt][2] = p0; lgP[mt][3] = p1;
                lgQ[mt][0] = q0; lgQ[mt][1] = q1; lgQ[mt][2] = q0; lgQ[mt][3] = q1;
            }
        }

        uint32_t b2P[2][2], b2Q[2][2];
#pragma unroll
        for (int kt = 0; kt < 8; ++kt) {
            if ((kt & 1) == 0) {
                uint32_t off = sw128(w2rowb + (uint32_t)(kt >> 1) * 64);
                ldsm_x4(sw2P + off, b2P[0][0], b2P[0][1], b2P[1][0], b2P[1][1]);
                ldsm_x4(sw2Q + off, b2Q[0][0], b2Q[0][1], b2Q[1][0], b2Q[1][1]);
            }
            uint32_t a2P[2][4], a2Q[2][4];
#pragma unroll
            for (int e = 0; e < 2; ++e) {
                const int nt = 2 * kt + e;
                uint32_t off0 = sw128((uint32_t)((nt * 8 + bjrow) * 128 + bkt * 32 + bkh * 16));
                uint32_t off1 = sw128((uint32_t)((nt * 8 + bjrow) * 128 + (bkt + 2) * 32 + bkh * 16));
                uint32_t bP[4][2], bQ[4][2];
                ldsm_x4(sb0 + off0, bP[0][0], bP[0][1], bP[1][0], bP[1][1]);
                ldsm_x4(sb0 + off1, bP[2][0], bP[2][1], bP[3][0], bP[3][1]);
                ldsm_x4(sb1 + off0, bQ[0][0], bQ[0][1], bQ[1][0], bQ[1][1]);
                ldsm_x4(sb1 + off1, bQ[2][0], bQ[2][1], bQ[3][0], bQ[3][1]);
#pragma unroll
                for (int mt = 0; mt < 2; ++mt) {
                    float dP0 = 0.f, dP1 = 0.f, dP2 = 0.f, dP3 = 0.f;
                    float dQ0 = 0.f, dQ1 = 0.f, dQ2 = 0.f, dQ3 = 0.f;
#pragma unroll
                    for (int k4 = 0; k4 < 4; ++k4) {
                        mma16816(dP0, dP1, dP2, dP3,
                                 a[mt][k4][0], a[mt][k4][1], a[mt][k4][2], a[mt][k4][3],
                                 bP[k4][0], bP[k4][1]);
                        mma16816(dQ0, dQ1, dQ2, dQ3,
                                 a[mt][k4][0], a[mt][k4][1], a[mt][k4][2], a[mt][k4][3],
                                 bQ[k4][0], bQ[k4][1]);
                    }
                    a2P[mt][2 * e]     = packh2(fmaxf(dP0, 0.f), fmaxf(dP1, 0.f));
                    a2P[mt][2 * e + 1] = packh2(fmaxf(dP2, 0.f), fmaxf(dP3, 0.f));
                    a2Q[mt][2 * e]     = packh2(fmaxf(dQ0, 0.f), fmaxf(dQ1, 0.f));
                    a2Q[mt][2 * e + 1] = packh2(fmaxf(dQ2, 0.f), fmaxf(dQ3, 0.f));
                }
            }
#pragma unroll
            for (int mt = 0; mt < 2; ++mt) {
                mma16816(lgP[mt][0], lgP[mt][1], lgP[mt][2], lgP[mt][3],
                         a2P[mt][0], a2P[mt][1], a2P[mt][2], a2P[mt][3],
                         b2P[kt & 1][0], b2P[kt & 1][1]);
                mma16816(lgQ[mt][0], lgQ[mt][1], lgQ[mt][2], lgQ[mt][3],
                         a2Q[mt][0], a2Q[mt][1], a2Q[mt][2], a2Q[mt][3],
                         b2Q[kt & 1][0], b2Q[kt & 1][1]);
            }
        }

#pragma unroll
        for (int mt = 0; mt < 2; ++mt) {
            float tP0 = __shfl_xor_sync(0xffffffffu, lgP[mt][0], 1);
            float tP2 = __shfl_xor_sync(0xffffffffu, lgP[mt][2], 1);
            float tQ0 = __shfl_xor_sync(0xffffffffu, lgQ[mt][0], 1);
            float tQ2 = __shfl_xor_sync(0xffffffffu, lgQ[mt][2], 1);
            if (quad == 0) {
                size_t rA = (size_t)(row0 + wid * 32 + mt * 16 + qrow);
                size_t rB = rA + 8;
                softmax_store(out, rA, nP, lgP[mt][0], lgP[mt][1], tP0);
                softmax_store(out, rB, nP, lgP[mt][2], lgP[mt][3], tP2);
                softmax_store(out, rA, nQ, lgQ[mt][0], lgQ[mt][1], tQ0);
                softmax_store(out, rB, nQ, lgQ[mt][2], lgQ[mt][3], tQ2);
            }
        }
        if (q < 23) CP_WAIT0();
        __syncthreads();

        pl = npl; group = ngroup; tile = ntile;
    }
}

// ============================================================================
extern "C" void kernel_launch(void* const* d_in, const int* in_sizes, int n_in,
                              void* d_out, int out_size)
{
    const float* x   = (const float*)d_in[0];
    const float* Cw1 = (const float*)d_in[1];
    const float* Cb1 = (const float*)d_in[2];
    const float* Cw2 = (const float*)d_in[3];
    const float* Cb2 = (const float*)d_in[4];
    const float* Nw1 = (const float*)d_in[5];
    const float* Nb1 = (const float*)d_in[6];
    const float* Nw2 = (const float*)d_in[7];
    const float* Nb2 = (const float*)d_in[8];
    const float* Fw1 = (const float*)d_in[9];
    const float* Fb1 = (const float*)d_in[10];
    const float* Fw2 = (const float*)d_in[11];
    const float* Fb2 = (const float*)d_in[12];
    const float* Ow1 = (const float*)d_in[13];
    const float* Ob1 = (const float*)d_in[14];
    const float* Ow2 = (const float*)d_in[15];
    const float* Ob2 = (const float*)d_in[16];
    float* out = (float*)d_out;

    cudaFuncSetAttribute(k_features, cudaFuncAttributeMaxDynamicSharedMemorySize, F_TOT);
    cudaFuncSetAttribute(k_ogemm,    cudaFuncAttributeMaxDynamicSharedMemorySize, OG_TOT);

    const int conv_elems = NB * 4096 + 4 * 4096 + NB * 512;   // 265216
    k_convert<<<(conv_elems + 255) / 256, 256>>>(Ow1, Ob1, Ow2, Nw1, Nb1, Nw2,
                                                 Fw1, Fb1, Fw2);

    k_features<<<NTILES, 256, F_TOT>>>(x, Cw1, Cb1, Cw2, Cb2, Nb2, Fb2);

    k_ogemm<<<OG_CTAS, 256, OG_TOT>>>(Ob2, out);
}

// round 17
// speedup vs baseline: 1.1490x; 1.0011x over previous
#include <cuda_runtime.h>
#include <cuda_fp16.h>
#include <cstdint>

#define NTILES 512
#define NB     54

// ========================= device scratch (fp16 images) =====================
__device__ __align__(16) __half g_w1h[NB * 8192];  // O_w1: [j=128][k=64], k57=Ob1
__device__ __align__(16) __half g_w2i[NB * 1024];  // O_w2: [n=8][k=128] (n<3 live)
__device__ __align__(16) __half g_bn1[8192];       // N_w1
__device__ __align__(16) __half g_bn2[8192];       // N_w2
__device__ __align__(16) __half g_bf1[8192];       // F_w1
__device__ __align__(16) __half g_bf2[8192];       // F_w2
__device__ __align__(16) __half g_fimg[NTILES * 8192]; // f images (swizzled, col57=1)

// ============================= PTX helpers =================================
__device__ __forceinline__ uint32_t smem_u32(const void* p) {
    uint32_t a;
    asm("{ .reg .u64 t; cvta.to.shared.u64 t, %1; cvt.u32.u64 %0, t; }"
        : "=r"(a) : "l"(p));
    return a;
}
__device__ __forceinline__ void ldsm_x4(uint32_t addr, uint32_t& r0, uint32_t& r1,
                                        uint32_t& r2, uint32_t& r3) {
    asm volatile("ldmatrix.sync.aligned.m8n8.x4.shared.b16 {%0,%1,%2,%3}, [%4];"
                 : "=r"(r0), "=r"(r1), "=r"(r2), "=r"(r3) : "r"(addr));
}
__device__ __forceinline__ void mma16816(float& d0, float& d1, float& d2, float& d3,
                                         uint32_t a0, uint32_t a1, uint32_t a2, uint32_t a3,
                                         uint32_t b0, uint32_t b1) {
    asm volatile("mma.sync.aligned.m16n8k16.row.col.f32.f16.f16.f32 "
                 "{%0,%1,%2,%3}, {%4,%5,%6,%7}, {%8,%9}, {%0,%1,%2,%3};"
                 : "+f"(d0), "+f"(d1), "+f"(d2), "+f"(d3)
                 : "r"(a0), "r"(a1), "r"(a2), "r"(a3), "r"(b0), "r"(b1));
}
__device__ __forceinline__ uint32_t sw128(uint32_t off) {
    return off ^ ((off >> 3) & 0x70);
}
__device__ __forceinline__ uint32_t packh2(float lo, float hi) {
    __half2 h = __floats2half2_rn(lo, hi);
    return *reinterpret_cast<uint32_t*>(&h);
}
#define CP_ASYNC16(dst, src) \
    asm volatile("cp.async.cg.shared.global [%0], [%1], 16;" \
                 :: "r"(dst), "l"(src) : "memory")
#define CP_COMMIT() asm volatile("cp.async.commit_group;" ::: "memory")
#define CP_WAIT0()  asm volatile("cp.async.wait_group 0;"  ::: "memory")

// ============================================================================
// Convert weights -> swizzled fp16 images (paired half2 stores; R16 proven).
// ============================================================================
__global__ __launch_bounds__(256) void k_convert(
    const float* __restrict__ Ow1, const float* __restrict__ Ob1,
    const float* __restrict__ Ow2,
    const float* __restrict__ Nw1, const float* __restrict__ Nb1,
    const float* __restrict__ Nw2,
    const float* __restrict__ Fw1, const float* __restrict__ Fb1,
    const float* __restrict__ Fw2)
{
    int idx = blockIdx.x * 256 + threadIdx.x;
    const int OW1P = NB * 4096;
    if (idx < OW1P) {
        int kp = idx & 31, j = (idx >> 5) & 127, n = idx >> 12;
        int k0 = kp * 2, k1 = k0 + 1;
        float v0 = (k0 < 57) ? Ow1[n * 7296 + k0 * 128 + j]
                 : (k0 == 57 ? Ob1[n * 128 + j] : 0.f);
        float v1 = (k1 < 57) ? Ow1[n * 7296 + k1 * 128 + j]
                 : (k1 == 57 ? Ob1[n * 128 + j] : 0.f);
        *(__half2*)((char*)g_w1h + n * 16384 + sw128((unsigned)(j * 128 + k0 * 2))) =
            __floats2half2_rn(v0, v1);
        return;
    }
    int t = idx - OW1P;
    if (t < 2 * 4096) {
        int img = t >> 12, e = t & 4095;
        int kp = e & 31, j = e >> 5;
        int k0 = kp * 2, k1 = k0 + 1;
        if (img == 0) {
            float v0 = (k0 < 54) ? Nw1[k0 * 128 + j] : (k0 == 54 ? Nb1[j] : 0.f);
            float v1 = (k1 < 54) ? Nw1[k1 * 128 + j] : (k1 == 54 ? Nb1[j] : 0.f);
            *(__half2*)((char*)g_bn1 + sw128((unsigned)(j * 128 + k0 * 2))) =
                __floats2half2_rn(v0, v1);
        } else {
            float v0 = (k0 < 57) ? Fw1[k0 * 128 + j] : (k0 == 57 ? Fb1[j] : 0.f);
            float v1 = (k1 < 57) ? Fw1[k1 * 128 + j] : (k1 == 57 ? Fb1[j] : 0.f);
            *(__half2*)((char*)g_bf1 + sw128((unsigned)(j * 128 + k0 * 2))) =
                __floats2half2_rn(v0, v1);
        }
        return;
    }
    t -= 2 * 4096;
    if (t < 2 * 4096) {
        int img = t >> 12, e = t & 4095;
        int kp = e & 63, m = e >> 6;
        int k0 = kp * 2, k1 = k0 + 1;
        if (img == 0) {
            float v0 = (m < 54) ? Nw2[k0 * 54 + m] : 0.f;
            float v1 = (m < 54) ? Nw2[k1 * 54 + m] : 0.f;
            *(__half2*)((char*)g_bn2 + sw128((unsigned)(m * 256 + k0 * 2))) =
                __floats2half2_rn(v0, v1);
        } else {
            float v0 = (m < 57) ? Fw2[k0 * 57 + m] : 0.f;
            float v1 = (m < 57) ? Fw2[k1 * 57 + m] : 0.f;
            *(__half2*)((char*)g_bf2 + sw128((unsigned)(m * 256 + k0 * 2))) =
                __floats2half2_rn(v0, v1);
        }
        return;
    }
    t -= 2 * 4096;
    if (t >= NB * 512) return;
    {
        int n = t >> 9, e = t & 511;
        int kp = e & 63, m = e >> 6;
        int k0 = kp * 2, k1 = k0 + 1;
        float v0 = (m < 3) ? Ow2[n * 384 + k0 * 3 + m] : 0.f;
        float v1 = (m < 3) ? Ow2[n * 384 + k1 * 3 + m] : 0.f;
        *(__half2*)((char*)g_w2i + n * 2048 + sw128((unsigned)(m * 256 + k0 * 2))) =
            __floats2half2_rn(v0, v1);
    }
}

// ==================== features-kernel SMEM layout (74.8 KB, 3 CTAs/SM) ======
#define FX    0          // 16 KB: x/f image
#define FW    16384      // 16 KB: single weight buffer (sequential loads)
#define FH0   32768      // 16 KB
#define FH1   49152      // 16 KB
#define FXC   65536      // 2048
#define FCW1  67584      // 2048
#define FCW2  69632      // 2048
#define FCB1  71680      // 512
#define FCB2  72192      // 32
#define FBN2  72224      // 256
#define FBF2  72480      // 256
#define FCP   72736      // 2048
#define F_TOT 74784

// ---- 8-warp layer: 64-K HMMA, 128 out cols, relu (bias baked) -> H0/H1 -----
__device__ __forceinline__ void layer_wide8(
    uint32_t sA, uint32_t sB, char* h0, char* h1, int wid, int lane)
{
    const int m01 = (lane >> 3) & 1, kh = lane >> 4;
    const int quad = lane & 3, qrow = lane >> 2;
    const int bjrow = lane & 7, bkt = lane >> 4, bkh = (lane >> 3) & 1;
    const int rg = wid * 16 + (lane & 7) + (m01 << 3);

    uint32_t a[4][4];
#pragma unroll
    for (int kt = 0; kt < 4; ++kt) {
        uint32_t off = sw128((uint32_t)(rg * 128 + kt * 32 + kh * 16));
        ldsm_x4(sA + off, a[kt][0], a[kt][1], a[kt][2], a[kt][3]);
    }
#pragma unroll 4
    for (int nt = 0; nt < 16; ++nt) {
        uint32_t off0 = sw128((uint32_t)((nt * 8 + bjrow) * 128 + bkt * 32 + bkh * 16));
        uint32_t off1 = sw128((uint32_t)((nt * 8 + bjrow) * 128 + (bkt + 2) * 32 + bkh * 16));
        uint32_t b[4][2];
        ldsm_x4(sB + off0, b[0][0], b[0][1], b[1][0], b[1][1]);
        ldsm_x4(sB + off1, b[2][0], b[2][1], b[3][0], b[3][1]);
        float d0 = 0.f, d1 = 0.f, d2 = 0.f, d3 = 0.f;
#pragma unroll
        for (int kt = 0; kt < 4; ++kt)
            mma16816(d0, d1, d2, d3, a[kt][0], a[kt][1], a[kt][2], a[kt][3],
                     b[kt][0], b[kt][1]);
        int j0 = nt * 8 + quad * 2;
        char* himg = (j0 < 64) ? h0 : h1;
        int   jc   = j0 & 63;
        int rA = wid * 16 + qrow, rB = rA + 8;
        *(__half2*)(himg + sw128((uint32_t)(rA * 128 + jc * 2))) =
            __floats2half2_rn(fmaxf(d0, 0.f), fmaxf(d1, 0.f));
        *(__half2*)(himg + sw128((uint32_t)(rB * 128 + jc * 2))) =
            __floats2half2_rn(fmaxf(d2, 0.f), fmaxf(d3, 0.f));
    }
}

// ---- 8-warp layer: 128-K HMMA (H halves), bias, fp16 -> outimg -------------
__device__ __forceinline__ void layer_narrow8(
    uint32_t sH0, uint32_t sH1, uint32_t sB, const float* __restrict__ bias,
    char* outimg, int coff, int mlim, int ntn, int wid, int lane)
{
    const int m01 = (lane >> 3) & 1, kh = lane >> 4;
    const int quad = lane & 3, qrow = lane >> 2;
    const int bjrow = lane & 7, bkt = lane >> 4, bkh = (lane >> 3) & 1;
    const int rg = wid * 16 + (lane & 7) + (m01 << 3);

    uint32_t a[8][4];
#pragma unroll
    for (int kt = 0; kt < 8; ++kt) {
        uint32_t src = (kt < 4) ? sH0 : sH1;
        int      ktl = kt & 3;
        uint32_t off = sw128((uint32_t)(rg * 128 + ktl * 32 + kh * 16));
        ldsm_x4(src + off, a[kt][0], a[kt][1], a[kt][2], a[kt][3]);
    }
    for (int nt = 0; nt < ntn; ++nt) {
        uint32_t b[8][2];
#pragma unroll
        for (int q = 0; q < 4; ++q) {
            uint32_t off = sw128((uint32_t)((nt * 8 + bjrow) * 256 + q * 64 + bkt * 32 + bkh * 16));
            ldsm_x4(sB + off, b[2 * q][0], b[2 * q][1], b[2 * q + 1][0], b[2 * q + 1][1]);
        }
        float d0 = 0.f, d1 = 0.f, d2 = 0.f, d3 = 0.f;
#pragma unroll
        for (int kt = 0; kt < 8; ++kt)
            mma16816(d0, d1, d2, d3, a[kt][0], a[kt][1], a[kt][2], a[kt][3],
                     b[kt][0], b[kt][1]);
        int m0 = nt * 8 + quad * 2, m1 = m0 + 1;
        int rA = wid * 16 + qrow, rB = rA + 8;
        if (m0 < mlim) {
            *(__half*)(outimg + sw128((uint32_t)(rA * 128 + (m0 + coff) * 2))) =
                __float2half(d0 + bias[m0]);
            *(__half*)(outimg + sw128((uint32_t)(rB * 128 + (m0 + coff) * 2))) =
                __float2half(d2 + bias[m0]);
        }
        if (m1 < mlim) {
            *(__half*)(outimg + sw128((uint32_t)(rA * 128 + (m1 + coff) * 2))) =
                __float2half(d1 + bias[m1]);
            *(__half*)(outimg + sw128((uint32_t)(rB * 128 + (m1 + coff) * 2))) =
                __float2half(d3 + bias[m1]);
        }
    }
}

__device__ __forceinline__ void softmax_store(float* __restrict__ out,
                                              size_t row, int n,
                                              float l0, float l1, float l2)
{
    float mx = fmaxf(l0, fmaxf(l1, l2));
    float e0 = __expf(l0 - mx), e1 = __expf(l1 - mx), e2 = __expf(l2 - mx);
    float inv = 1.f / (e0 + e1 + e2);
    float* o = out + row * 162 + n * 3;
    o[0] = e0 * inv; o[1] = e1 * inv; o[2] = e2 * inv;
}

// ============================================================================
// Kernel 1: features, 256 threads / 8 warps, 128 rows; single weight buffer,
// 3 CTAs/SM (occupancy over double-buffering).
// ============================================================================
__global__ void __launch_bounds__(256, 3) k_features(
    const float* __restrict__ x,
    const float* __restrict__ Cw1, const float* __restrict__ Cb1v,
    const float* __restrict__ Cw2, const float* __restrict__ Cb2v,
    const float* __restrict__ Nb2v, const float* __restrict__ Fb2v)
{
    extern __shared__ char smem[];
    const uint32_t sbase = smem_u32(smem);
    float* xc   = (float*)(smem + FXC);
    float* cw1t = (float*)(smem + FCW1);
    float* cw2  = (float*)(smem + FCW2);
    float* cb1  = (float*)(smem + FCB1);
    float* cb2  = (float*)(smem + FCB2);
    float* bn2  = (float*)(smem + FBN2);
    float* bf2  = (float*)(smem + FBF2);
    float* cp   = (float*)(smem + FCP);

    const int tid  = threadIdx.x;
    const int wid  = tid >> 5;
    const int lane = tid & 31;
    const int row0 = blockIdx.x * 128;

    // ---------------- phase 0: x image + Nw1 + small consts -----------------
    for (int i = tid; i < 128 * 58; i += 256) {
        int r = i / 58, c = i - r * 58;
        float v = x[(size_t)(row0 + r) * 58 + c];
        if (c < 4) xc[r * 4 + c] = v;
        else *(__half*)(smem + FX + sw128((uint32_t)(r * 128 + (c - 4) * 2))) =
                 __float2half(v);
    }
    for (int i = tid; i < 128 * 10; i += 256) {
        int r = i / 10, kk = 54 + (i - (i / 10) * 10);
        float v = (kk == 54 || kk == 57) ? 1.f : 0.f;
        *(__half*)(smem + FX + sw128((uint32_t)(r * 128 + kk * 2))) = __float2half(v);
    }
    {
        const uint4* s = (const uint4*)g_bn1; uint4* d = (uint4*)(smem + FW);
#pragma unroll
        for (int i = 0; i < 4; ++i) d[tid + 256 * i] = s[tid + 256 * i];
    }
    if (tid < 128) cb1[tid] = Cb1v[tid];
    else if (tid < 192) {
        int t = tid - 128;
        bn2[t] = (t < 54) ? Nb2v[t] : 0.f;
        bf2[t] = (t < 57) ? Fb2v[t] : 0.f;
    } else if (tid < 196) {
        int t = tid - 192;
        cb2[t] = (t < 3) ? Cb2v[t] : 0.f;
    }
    for (int i = tid; i < 512; i += 256) { int k = i >> 7, j = i & 127; cw1t[j * 4 + k] = Cw1[i]; }
    for (int i = tid; i < 384; i += 256) { int j = i / 3, m = i - j * 3; cw2[j * 4 + m] = Cw2[i]; }
    __syncthreads();

    // ---------------- stage C: 2 threads per row (split j) ------------------
    const int crow = tid & 127, cjh = tid >> 7;
    float c0, c1, c2;
    {
        float cx0 = xc[crow * 4 + 0], cx1 = xc[crow * 4 + 1];
        float cx2 = xc[crow * 4 + 2], cx3 = xc[crow * 4 + 3];
        c0 = cjh ? 0.f : cb2[0];
        c1 = cjh ? 0.f : cb2[1];
        c2 = cjh ? 0.f : cb2[2];
        const int j0 = cjh * 64;
        for (int j = j0; j < j0 + 64; ++j) {
            const float* w = &cw1t[j * 4];
            float h = cb1[j] + cx0 * w[0] + cx1 * w[1] + cx2 * w[2] + cx3 * w[3];
            h = fmaxf(h, 0.f);
            const float* w2 = &cw2[j * 4];
            c0 += h * w2[0]; c1 += h * w2[1]; c2 += h * w2[2];
        }
        if (cjh) {
            cp[crow * 4 + 0] = c0; cp[crow * 4 + 1] = c1; cp[crow * 4 + 2] = c2;
        }
    }

    // ---------------- N1: X @ Nw1(FW) -> H -----------------------------------
    layer_wide8(sbase + FX, sbase + FW, smem + FH0, smem + FH1, wid, lane);
    __syncthreads();
    {   // Nw2 -> FW
        const uint4* s = (const uint4*)g_bn2; uint4* d = (uint4*)(smem + FW);
#pragma unroll
        for (int i = 0; i < 4; ++i) d[tid + 256 * i] = s[tid + 256 * i];
    }
    __syncthreads();

    // ---------------- N2 -> X cols 3..56; c -> cols 0..2 ---------------------
    layer_narrow8(sbase + FH0, sbase + FH1, sbase + FW, bn2,
                  smem + FX, 3, 54, 7, wid, lane);
    if (!cjh) {
        float f0 = c0 + cp[crow * 4 + 0];
        float f1 = c1 + cp[crow * 4 + 1];
        float f2 = c2 + cp[crow * 4 + 2];
        *(__half*)(smem + FX + sw128((uint32_t)(crow * 128 + 0))) = __float2half(f0);
        *(__half*)(smem + FX + sw128((uint32_t)(crow * 128 + 2))) = __float2half(f1);
        *(__half*)(smem + FX + sw128((uint32_t)(crow * 128 + 4))) = __float2half(f2);
    }
    __syncthreads();
    {   // Fw1 -> FW
        const uint4* s = (const uint4*)g_bf1; uint4* d = (uint4*)(smem + FW);
#pragma unroll
        for (int i = 0; i < 4; ++i) d[tid + 256 * i] = s[tid + 256 * i];
    }
    __syncthreads();

    // ---------------- F1 -> H -------------------------------------------------
    layer_wide8(sbase + FX, sbase + FW, smem + FH0, smem + FH1, wid, lane);
    __syncthreads();
    {   // Fw2 -> FW
        const uint4* s = (const uint4*)g_bf2; uint4* d = (uint4*)(smem + FW);
#pragma unroll
        for (int i = 0; i < 4; ++i) d[tid + 256 * i] = s[tid + 256 * i];
    }
    __syncthreads();

    // ---------------- F2 -> X cols 0..56 (col57 stays 1) ----------------------
    layer_narrow8(sbase + FH0, sbase + FH1, sbase + FW, bf2,
                  smem + FX, 0, 57, 8, wid, lane);
    __syncthreads();

    {
        const uint4* s = (const uint4*)(smem + FX);
        uint4* d = (uint4*)(g_fimg + (size_t)blockIdx.x * 8192);
#pragma unroll
        for (int i = 0; i < 4; ++i) d[tid + 256 * i] = s[tid + 256 * i];
    }
}

// ==================== O-kernel SMEM layout (106.5 KB, 2 CTAs/SM) ============
#define OG_A    0          // 32 KB: two A tile images (256 rows)
#define OG_B0   32768      // 32 KB: pairbuf0 (branches P,Q contiguous)
#define OG_B2   65536      // 32 KB: pairbuf1
#define OG_W2S  98304      // 8 KB
#define OG_TOT  106496

#define OG_CTAS 288        // persistent: 288 CTAs x 24 pairs = 6912 = 256*9*3

// ============================================================================
// Kernel 2: O stage, PERSISTENT + cp.async (R16 proven, unchanged).
// ============================================================================
__global__ void __launch_bounds__(256, 2) k_ogemm(
    const float* __restrict__ Ob2, float* __restrict__ out)
{
    extern __shared__ char smem[];
    const uint32_t sbase = smem_u32(smem);

    const int tid  = threadIdx.x;
    const int wid  = tid >> 5;
    const int lane = tid & 31;

    const int qbase = blockIdx.x * 24;
    int item  = qbase / 3;
    int pl    = 0;
    int tile  = item / 9;
    int group = item - tile * 9;

    const int quad = lane & 3;
    const int qrow = lane >> 2;
    const int bjrow = lane & 7;
    const int bkt   = lane >> 4;
    const int bkh   = (lane >> 3) & 1;
    const uint32_t w2rowb = (uint32_t)((lane & 7) * 256 + (lane >> 3) * 16);
    const int m01 = (lane >> 3) & 1, kh = lane >> 4;

    {
        const uint4* sa = (const uint4*)(g_fimg + (size_t)tile * 16384);
        uint4* dx = (uint4*)(smem + OG_A);
#pragma unroll
        for (int i = 0; i < 8; ++i) dx[tid + 256 * i] = sa[tid + 256 * i];
        int nP0 = group * 6;
        const uint4* s0 = (const uint4*)(g_w1h + nP0 * 8192);
        uint4* d0 = (uint4*)(smem + OG_B0);
#pragma unroll
        for (int i = 0; i < 8; ++i) d0[tid + 256 * i] = s0[tid + 256 * i];
        ((uint4*)(smem + OG_W2S))[tid] = ((const uint4*)(g_w2i + nP0 * 1024))[tid];
    }
    __syncthreads();

    uint32_t a[2][4][4];
#pragma unroll
    for (int mt = 0; mt < 2; ++mt) {
        int rg = wid * 32 + mt * 16 + (lane & 7) + (m01 << 3);
        uint32_t base = sbase + OG_A + (uint32_t)(rg >> 7) * 16384;
        int rl = rg & 127;
#pragma unroll
        for (int kt = 0; kt < 4; ++kt) {
            uint32_t off = sw128((uint32_t)(rl * 128 + kt * 32 + kh * 16));
            ldsm_x4(base + off,
                    a[mt][kt][0], a[mt][kt][1], a[mt][kt][2], a[mt][kt][3]);
        }
    }
    __syncthreads();

    int frag_tile = tile;

    for (int q = 0; q < 24; ++q) {
        const int buf = q & 1, nxt = buf ^ 1;
        const int nP = group * 6 + pl * 2, nQ = nP + 1;
        const int row0 = tile * 256;

        if (tile != frag_tile) {
#pragma unroll
            for (int mt = 0; mt < 2; ++mt) {
                int rg = wid * 32 + mt * 16 + (lane & 7) + (m01 << 3);
                uint32_t base = sbase + OG_A + (uint32_t)(rg >> 7) * 16384;
                int rl = rg & 127;
#pragma unroll
                for (int kt = 0; kt < 4; ++kt) {
                    uint32_t off = sw128((uint32_t)(rl * 128 + kt * 32 + kh * 16));
                    ldsm_x4(base + off,
                            a[mt][kt][0], a[mt][kt][1], a[mt][kt][2], a[mt][kt][3]);
                }
            }
            frag_tile = tile;
            __syncthreads();
        }

        int npl = pl + 1, ngroup = group, ntile = tile;
        if (npl == 3) { npl = 0; ++ngroup; if (ngroup == 9) { ngroup = 0; ++ntile; } }
        if (q < 23) {
            int nPn = ngroup * 6 + npl * 2;
            uint32_t db = sbase + (nxt ? OG_B2 : OG_B0);
            const char* sg = (const char*)(g_w1h + nPn * 8192);
#pragma unroll
            for (int i = 0; i < 8; ++i) {
                uint32_t o = (uint32_t)(tid + 256 * i) * 16;
                CP_ASYNC16(db + o, sg + o);
            }
            CP_ASYNC16(sbase + OG_W2S + (uint32_t)nxt * 4096 + (uint32_t)tid * 16,
                       (const char*)(g_w2i + nPn * 1024) + tid * 16);
            if (ntile != tile) {
                const char* sa = (const char*)(g_fimg + (size_t)ntile * 16384);
#pragma unroll
                for (int i = 0; i < 8; ++i) {
                    uint32_t o = (uint32_t)(tid + 256 * i) * 16;
                    CP_ASYNC16(sbase + OG_A + o, sa + o);
                }
            }
            CP_COMMIT();
        }

        const uint32_t sb0  = sbase + (buf ? OG_B2 : OG_B0);
        const uint32_t sb1  = sb0 + 16384;
        const uint32_t sw2P = sbase + OG_W2S + (uint32_t)buf * 4096;
        const uint32_t sw2Q = sw2P + 2048;

        float lgP[2][4], lgQ[2][4];
        {
            int cc0 = 2 * quad, cc1 = cc0 + 1;
            float p0 = (cc0 < 3) ? Ob2[nP * 3 + cc0] : 0.f;
            float p1 = (cc1 < 3) ? Ob2[nP * 3 + cc1] : 0.f;
            float q0 = (cc0 < 3) ? Ob2[nQ * 3 + cc0] : 0.f;
            float q1 = (cc1 < 3) ? Ob2[nQ * 3 + cc1] : 0.f;
#pragma unroll
            for (int mt = 0; mt < 2; ++mt) {
                lgP[mt][0] = p0; lgP[mt][1] = p1; lgP[mt][2] = p0; lgP[mt][3] = p1;
                lgQ[mt][0] = q0; lgQ[mt][1] = q1; lgQ[mt][2] = q0; lgQ[mt][3] = q1;
            }
        }

        uint32_t b2P[2][2], b2Q[2][2];
#pragma unroll
        for (int kt = 0; kt < 8; ++kt) {
            if ((kt & 1) == 0) {
                uint32_t off = sw128(w2rowb + (uint32_t)(kt >> 1) * 64);
                ldsm_x4(sw2P + off, b2P[0][0], b2P[0][1], b2P[1][0], b2P[1][1]);
                ldsm_x4(sw2Q + off, b2Q[0][0], b2Q[0][1], b2Q[1][0], b2Q[1][1]);
            }
            uint32_t a2P[2][4], a2Q[2][4];
#pragma unroll
            for (int e = 0; e < 2; ++e) {
                const int nt = 2 * kt + e;
                uint32_t off0 = sw128((uint32_t)((nt * 8 + bjrow) * 128 + bkt * 32 + bkh * 16));
                uint32_t off1 = sw128((uint32_t)((nt * 8 + bjrow) * 128 + (bkt + 2) * 32 + bkh * 16));
                uint32_t bP[4][2], bQ[4][2];
                ldsm_x4(sb0 + off0, bP[0][0], bP[0][1], bP[1][0], bP[1][1]);
                ldsm_x4(sb0 + off1, bP[2][0], bP[2][1], bP[3][0], bP[3][1]);
                ldsm_x4(sb1 + off0, bQ[0][0], bQ[0][1], bQ[1][0], bQ[1][1]);
                ldsm_x4(sb1 + off1, bQ[2][0], bQ[2][1], bQ[3][0], bQ[3][1]);
#pragma unroll
                for (int mt = 0; mt < 2; ++mt) {
                    float dP0 = 0.f, dP1 = 0.f, dP2 = 0.f, dP3 = 0.f;
                    float dQ0 = 0.f, dQ1 = 0.f, dQ2 = 0.f, dQ3 = 0.f;
#pragma unroll
                    for (int k4 = 0; k4 < 4; ++k4) {
                        mma16816(dP0, dP1, dP2, dP3,
                                 a[mt][k4][0], a[mt][k4][1], a[mt][k4][2], a[mt][k4][3],
                                 bP[k4][0], bP[k4][1]);
                        mma16816(dQ0, dQ1, dQ2, dQ3,
                                 a[mt][k4][0], a[mt][k4][1], a[mt][k4][2], a[mt][k4][3],
                                 bQ[k4][0], bQ[k4][1]);
                    }
                    a2P[mt][2 * e]     = packh2(fmaxf(dP0, 0.f), fmaxf(dP1, 0.f));
                    a2P[mt][2 * e + 1] = packh2(fmaxf(dP2, 0.f), fmaxf(dP3, 0.f));
                    a2Q[mt][2 * e]     = packh2(fmaxf(dQ0, 0.f), fmaxf(dQ1, 0.f));
                    a2Q[mt][2 * e + 1] = packh2(fmaxf(dQ2, 0.f), fmaxf(dQ3, 0.f));
                }
            }
#pragma unroll
            for (int mt = 0; mt < 2; ++mt) {
                mma16816(lgP[mt][0], lgP[mt][1], lgP[mt][2], lgP[mt][3],
                         a2P[mt][0], a2P[mt][1], a2P[mt][2], a2P[mt][3],
                         b2P[kt & 1][0], b2P[kt & 1][1]);
                mma16816(lgQ[mt][0], lgQ[mt][1], lgQ[mt][2], lgQ[mt][3],
                         a2Q[mt][0], a2Q[mt][1], a2Q[mt][2], a2Q[mt][3],
                         b2Q[kt & 1][0], b2Q[kt & 1][1]);
            }
        }

#pragma unroll
        for (int mt = 0; mt < 2; ++mt) {
            float tP0 = __shfl_xor_sync(0xffffffffu, lgP[mt][0], 1);
            float tP2 = __shfl_xor_sync(0xffffffffu, lgP[mt][2], 1);
            float tQ0 = __shfl_xor_sync(0xffffffffu, lgQ[mt][0], 1);
            float tQ2 = __shfl_xor_sync(0xffffffffu, lgQ[mt][2], 1);
            if (quad == 0) {
                size_t rA = (size_t)(row0 + wid * 32 + mt * 16 + qrow);
                size_t rB = rA + 8;
                softmax_store(out, rA, nP, lgP[mt][0], lgP[mt][1], tP0);
                softmax_store(out, rB, nP, lgP[mt][2], lgP[mt][3], tP2);
                softmax_store(out, rA, nQ, lgQ[mt][0], lgQ[mt][1], tQ0);
                softmax_store(out, rB, nQ, lgQ[mt][2], lgQ[mt][3], tQ2);
            }
        }
        if (q < 23) CP_WAIT0();
        __syncthreads();

        pl = npl; group = ngroup; tile = ntile;
    }
}

// ============================================================================
extern "C" void kernel_launch(void* const* d_in, const int* in_sizes, int n_in,
                              void* d_out, int out_size)
{
    const float* x   = (const float*)d_in[0];
    const float* Cw1 = (const float*)d_in[1];
    const float* Cb1 = (const float*)d_in[2];
    const float* Cw2 = (const float*)d_in[3];
    const float* Cb2 = (const float*)d_in[4];
    const float* Nw1 = (const float*)d_in[5];
    const float* Nb1 = (const float*)d_in[6];
    const float* Nw2 = (const float*)d_in[7];
    const float* Nb2 = (const float*)d_in[8];
    const float* Fw1 = (const float*)d_in[9];
    const float* Fb1 = (const float*)d_in[10];
    const float* Fw2 = (const float*)d_in[11];
    const float* Fb2 = (const float*)d_in[12];
    const float* Ow1 = (const float*)d_in[13];
    const float* Ob1 = (const float*)d_in[14];
    const float* Ow2 = (const float*)d_in[15];
    const float* Ob2 = (const float*)d_in[16];
    float* out = (float*)d_out;

    cudaFuncSetAttribute(k_features, cudaFuncAttributeMaxDynamicSharedMemorySize, F_TOT);
    cudaFuncSetAttribute(k_ogemm,    cudaFuncAttributeMaxDynamicSharedMemorySize, OG_TOT);

    const int conv_elems = NB * 4096 + 4 * 4096 + NB * 512;   // 265216
    k_convert<<<(conv_elems + 255) / 256, 256>>>(Ow1, Ob1, Ow2, Nw1, Nb1, Nw2,
                                                 Fw1, Fb1, Fw2);

    k_features<<<NTILES, 256, F_TOT>>>(x, Cw1, Cb1, Cw2, Cb2, Nb2, Fb2);

    k_ogemm<<<OG_CTAS, 256, OG_TOT>>>(Ob2, out);
}